// round 11
// baseline (speedup 1.0000x reference)
#include <cuda_runtime.h>
#include <cuda_bf16.h>
#include <cstdint>

#define N_NODES 100000
#define N_EDGES 1600000
#define FEAT 128
#define N_GRAPHS 100

#define SCAN_ITEMS 1024
#define SCAN_BLOCKS ((N_NODES + SCAN_ITEMS - 1) / SCAN_ITEMS)  // 98

// Scratch (allocation-free rule: __device__ globals)
__device__ float g_bufB[(size_t)N_NODES * FEAT];
__device__ int   g_deg[N_NODES];
__device__ int   g_rowptr[N_NODES + 1];
__device__ int   g_cursor[N_NODES];
__device__ int   g_csrsrc[N_EDGES];
__device__ int   g_blocksum[SCAN_BLOCKS];
__device__ int   g_blockoff[SCAN_BLOCKS];
__device__ int   g_idx64;

// ===========================================================================
// Helpers
// ===========================================================================
__device__ __forceinline__ uint32_t smem_u32(const void* p) {
    uint32_t a;
    asm("{ .reg .u64 t; cvta.to.shared.u64 t, %1; cvt.u32.u64 %0, t; }" : "=r"(a) : "l"(p));
    return a;
}
__device__ __forceinline__ uint32_t pack_bf16(float a, float b) {  // {lo=a, hi=b}
    uint32_t r;
    asm("cvt.rn.bf16x2.f32 %0, %1, %2;" : "=r"(r) : "f"(b), "f"(a));
    return r;
}
__device__ __forceinline__ void ldsm_x4(uint32_t* r, uint32_t addr) {
    asm volatile("ldmatrix.sync.aligned.m8n8.x4.shared.b16 {%0,%1,%2,%3}, [%4];"
        : "=r"(r[0]), "=r"(r[1]), "=r"(r[2]), "=r"(r[3]) : "r"(addr));
}
__device__ __forceinline__ void mma_bf16(float* c, const uint32_t* a, const uint32_t* b) {
    asm volatile("mma.sync.aligned.m16n8k16.row.col.f32.bf16.bf16.f32 "
        "{%0,%1,%2,%3}, {%4,%5,%6,%7}, {%8,%9}, {%0,%1,%2,%3};"
        : "+f"(c[0]), "+f"(c[1]), "+f"(c[2]), "+f"(c[3])
        : "r"(a[0]), "r"(a[1]), "r"(a[2]), "r"(a[3]), "r"(b[0]), "r"(b[1]));
}
#define BAR_CONS() asm volatile("bar.sync 1, 256;" ::: "memory")

// ===========================================================================
// Index dtype detector (int64 little-endian => odd words zero). 1 warp.
// ===========================================================================
__global__ void detect_kernel(const int* __restrict__ ei_words) {
    const int lane = threadIdx.x;
    int ok = 1;
#pragma unroll
    for (int j = 0; j < 16; j++) {
        int i = j * 32 + lane;
        int lo = ei_words[2 * i];
        int hi = ei_words[2 * i + 1];
        if (hi != 0 || lo < 0 || lo >= N_NODES) ok = 0;
    }
    int all = __all_sync(0xffffffffu, ok);
    if (lane == 0) g_idx64 = all;
}
__device__ __forceinline__ int load_idx(const void* p, long long i) {
    return g_idx64 ? (int)((const long long*)p)[i] : ((const int*)p)[i];
}

// ===========================================================================
// CSR build
// ===========================================================================
__global__ void hist_kernel(const void* __restrict__ ei, int* __restrict__ deg) {
    int e = blockIdx.x * blockDim.x + threadIdx.x;
    if (e >= N_EDGES) return;
    atomicAdd(&deg[load_idx(ei, (long long)N_EDGES + e)], 1);
}
__global__ void scanA_kernel(const int* __restrict__ deg, int* __restrict__ blocksum) {
    __shared__ int red[256];
    const int t = threadIdx.x;
    const int base = blockIdx.x * SCAN_ITEMS;
    int s = 0;
#pragma unroll
    for (int j = 0; j < 4; j++) {
        int i = base + t + j * 256;
        if (i < N_NODES) s += deg[i];
    }
    red[t] = s;
    __syncthreads();
    for (int off = 128; off > 0; off >>= 1) {
        if (t < off) red[t] += red[t + off];
        __syncthreads();
    }
    if (t == 0) blocksum[blockIdx.x] = red[0];
}
__global__ void scanB_kernel(const int* __restrict__ blocksum,
                             int* __restrict__ blockoff, int* __restrict__ rowptr) {
    __shared__ int v[128];
    const int t = threadIdx.x;
    v[t] = (t < SCAN_BLOCKS) ? blocksum[t] : 0;
    __syncthreads();
    int mine = v[t];
    for (int off = 1; off < 128; off <<= 1) {
        int tmp = (t >= off) ? v[t - off] : 0;
        __syncthreads();
        v[t] += tmp;
        __syncthreads();
    }
    if (t < SCAN_BLOCKS) blockoff[t] = v[t] - mine;
    if (t == 127) rowptr[N_NODES] = v[127];
}
__global__ void scanC_kernel(const int* __restrict__ deg, const int* __restrict__ blockoff,
                             int* __restrict__ rowptr, int* __restrict__ cursor) {
    __shared__ int ts[256];
    const int t = threadIdx.x;
    const int base = blockIdx.x * SCAN_ITEMS + t * 4;
    int d0 = 0, d1 = 0, d2 = 0, d3 = 0;
    if (base + 0 < N_NODES) d0 = deg[base + 0];
    if (base + 1 < N_NODES) d1 = deg[base + 1];
    if (base + 2 < N_NODES) d2 = deg[base + 2];
    if (base + 3 < N_NODES) d3 = deg[base + 3];
    int tot = d0 + d1 + d2 + d3;
    ts[t] = tot;
    __syncthreads();
    for (int off = 1; off < 256; off <<= 1) {
        int tmp = (t >= off) ? ts[t - off] : 0;
        __syncthreads();
        ts[t] += tmp;
        __syncthreads();
    }
    int run = blockoff[blockIdx.x] + ts[t] - tot;
    if (base + 0 < N_NODES) { rowptr[base + 0] = run; cursor[base + 0] = run; run += d0; }
    if (base + 1 < N_NODES) { rowptr[base + 1] = run; cursor[base + 1] = run; run += d1; }
    if (base + 2 < N_NODES) { rowptr[base + 2] = run; cursor[base + 2] = run; run += d2; }
    if (base + 3 < N_NODES) { rowptr[base + 3] = run; cursor[base + 3] = run; run += d3; }
}
__global__ void fill_kernel(const void* __restrict__ ei,
                            int* __restrict__ cursor, int* __restrict__ csrsrc) {
    int e = blockIdx.x * blockDim.x + threadIdx.x;
    if (e >= N_EDGES) return;
    int s = load_idx(ei, e);
    int d = load_idx(ei, (long long)N_EDGES + e);
    csrsrc[atomicAdd(&cursor[d], 1)] = s;
}

// ===========================================================================
// Warp-specialized fused GIN layer (persistent):
//   z = x + sum_neighbors x ;  C = relu( relu(z@W1^T + b1) @ W2^T + b2 )
// 512 threads: warps 0-7 MMA consumers, warps 8-15 gather producers.
// Producers aggregate the NEXT 64-row tile and write the bf16 (hi,lo) split
// directly into the double-buffered smem A tiles; consumers run the two
// bf16-split HMMA GEMMs on the current tile.
// ===========================================================================
#define SAB 136
#define WTILE_B (128 * SAB * 2)            // 34816
#define ATILE_B (64 * SAB * 2)             // 17408
#define SMF_B1   0
#define SMF_B2   512
#define SMF_W1H  1024
#define SMF_W1L  (SMF_W1H + WTILE_B)
#define SMF_W2H  (SMF_W1H + 2 * WTILE_B)
#define SMF_W2L  (SMF_W1H + 3 * WTILE_B)
#define SMF_A0H  (SMF_W1H + 4 * WTILE_B)   // 140288
#define SMF_A0L  (SMF_A0H + ATILE_B)
#define SMF_A1H  (SMF_A0H + 2 * ATILE_B)
#define SMF_A1L  (SMF_A0H + 3 * ATILE_B)
#define SMF_TOTAL (SMF_A0H + 4 * ATILE_B)  // 209920
#define GEMM_GRID 148

// Producer gather: aggregate rows [row0+wp*8, row0+wp*8+8) and write split
// bf16 into smem A buffer (ah/al byte offsets within dynamic smem).
__device__ __forceinline__ void gather_tile(const float* __restrict__ X,
                                            char* smem, uint32_t ah, uint32_t al,
                                            int row0, int M, int wp, int lane,
                                            const int* __restrict__ rowptr,
                                            const int* __restrict__ csrsrc) {
#pragma unroll
    for (int i = 0; i < 8; i++) {
        const int n = row0 + wp * 8 + i;
        if (n >= M) return;
        const int beg = rowptr[n];
        const int end = rowptr[n + 1];
        float4 acc = ((const float4*)(X + (size_t)n * FEAT))[lane];
        for (int base = beg; base < end; base += 32) {
            const int cnt = min(32, end - base);
            int sid = (base + lane < end) ? csrsrc[base + lane] : 0;
#pragma unroll 4
            for (int j = 0; j < cnt; j++) {
                int s = __shfl_sync(0xffffffffu, sid, j);
                float4 v = ((const float4*)(X + (size_t)s * FEAT))[lane];
                acc.x += v.x; acc.y += v.y; acc.z += v.z; acc.w += v.w;
            }
        }
        float h0 = __bfloat162float(__float2bfloat16_rn(acc.x));
        float h1 = __bfloat162float(__float2bfloat16_rn(acc.y));
        float h2 = __bfloat162float(__float2bfloat16_rn(acc.z));
        float h3 = __bfloat162float(__float2bfloat16_rn(acc.w));
        const uint32_t off = (uint32_t)((n - row0) * SAB + lane * 4) * 2;
        *(uint2*)(smem + ah + off) = make_uint2(pack_bf16(h0, h1), pack_bf16(h2, h3));
        *(uint2*)(smem + al + off) =
            make_uint2(pack_bf16(acc.x - h0, acc.y - h1), pack_bf16(acc.z - h2, acc.w - h3));
    }
}

__global__ void __launch_bounds__(512)
gin_layer_kernel(const float* __restrict__ X,
                 const float* __restrict__ W1, const float* __restrict__ b1,
                 const float* __restrict__ W2, const float* __restrict__ b2,
                 float* __restrict__ C, int M,
                 const int* __restrict__ rowptr, const int* __restrict__ csrsrc) {
    extern __shared__ char smem[];
    const uint32_t sb = smem_u32(smem);
    const int tid = threadIdx.x;
    const int lane = tid & 31;
    const int wid = tid >> 5;
    const bool isProd = (wid >= 8);
    const int numTiles = (M + 63) >> 6;

    const uint32_t AH[2] = {SMF_A0H, SMF_A1H};
    const uint32_t AL[2] = {SMF_A0L, SMF_A1L};

    const int tile0 = blockIdx.x;

    if (!isProd) {
        // ---- consumers: biases + one-time W1/W2 split-convert ----
        if (tid < 128) ((float*)(smem + SMF_B1))[tid] = b1[tid];
        else           ((float*)(smem + SMF_B2))[tid - 128] = b2[tid - 128];
        const int r = tid >> 1;
        const int half = tid & 1;
        const float4* w1row = (const float4*)(W1 + (size_t)r * FEAT);
        const float4* w2row = (const float4*)(W2 + (size_t)r * FEAT);
#pragma unroll
        for (int j = 0; j < 16; j++) {
            const int col = half * 64 + j * 4;
            const uint32_t off = (uint32_t)(r * SAB + col) * 2;
            float4 v1 = w1row[half * 16 + j];
            float a0 = __bfloat162float(__float2bfloat16_rn(v1.x));
            float a1 = __bfloat162float(__float2bfloat16_rn(v1.y));
            float a2 = __bfloat162float(__float2bfloat16_rn(v1.z));
            float a3 = __bfloat162float(__float2bfloat16_rn(v1.w));
            *(uint2*)(smem + SMF_W1H + off) = make_uint2(pack_bf16(a0, a1), pack_bf16(a2, a3));
            *(uint2*)(smem + SMF_W1L + off) =
                make_uint2(pack_bf16(v1.x - a0, v1.y - a1), pack_bf16(v1.z - a2, v1.w - a3));
            float4 v2 = w2row[half * 16 + j];
            float c0 = __bfloat162float(__float2bfloat16_rn(v2.x));
            float c1 = __bfloat162float(__float2bfloat16_rn(v2.y));
            float c2 = __bfloat162float(__float2bfloat16_rn(v2.z));
            float c3 = __bfloat162float(__float2bfloat16_rn(v2.w));
            *(uint2*)(smem + SMF_W2H + off) = make_uint2(pack_bf16(c0, c1), pack_bf16(c2, c3));
            *(uint2*)(smem + SMF_W2L + off) =
                make_uint2(pack_bf16(v2.x - c0, v2.y - c1), pack_bf16(v2.z - c2, v2.w - c3));
        }
    } else {
        // ---- producers: gather first tile into buffer 0 ----
        if (tile0 < numTiles)
            gather_tile(X, smem, AH[0], AL[0], tile0 << 6, M, wid - 8, lane, rowptr, csrsrc);
    }
    __syncthreads();

    // ---- consumer warp tiling constants ----
    const int m0 = (wid & 1) * 32;
    const int n0 = (wid >> 1) * 32;   // valid for wid<8
    const int g = lane >> 3, rr = lane & 7;
    uint32_t aH0[2][2], aL0[2][2], b1H[2], b1L[2], b2H[2], b2L[2];
#pragma unroll
    for (int b = 0; b < 2; b++)
#pragma unroll
        for (int mb = 0; mb < 2; mb++) {
            const uint32_t o =
                (uint32_t)((m0 + mb * 16 + (g & 1) * 8 + rr) * SAB + (g >> 1) * 8) * 2;
            aH0[b][mb] = sb + AH[b] + o;
            aL0[b][mb] = sb + AL[b] + o;
        }
#pragma unroll
    for (int p = 0; p < 2; p++) {
        const uint32_t o = (uint32_t)(((n0 & 96) + p * 16 + (g >> 1) * 8 + rr) * SAB + (g & 1) * 8) * 2;
        b1H[p] = sb + SMF_W1H + o;
        b1L[p] = sb + SMF_W1L + o;
        b2H[p] = sb + SMF_W2H + o;
        b2L[p] = sb + SMF_W2L + o;
    }
    const float* bs1 = (const float*)(smem + SMF_B1);
    const float* bs2 = (const float*)(smem + SMF_B2);

    // ---- persistent tile loop ----
    int cur = 0;
    for (int t = tile0; t < numTiles; t += GEMM_GRID, cur ^= 1) {
        const int row0 = t << 6;

        if (isProd) {
            // gather NEXT tile into the other buffer (overlaps consumer GEMMs)
            const int nt = t + GEMM_GRID;
            if (nt < numTiles)
                gather_tile(X, smem, AH[cur ^ 1], AL[cur ^ 1], nt << 6, M,
                            wid - 8, lane, rowptr, csrsrc);
        } else {
            // ================= GEMM1: acc = A @ W1^T =================
            float acc[2][4][4];
#pragma unroll
            for (int mb = 0; mb < 2; mb++)
#pragma unroll
                for (int o = 0; o < 4; o++)
#pragma unroll
                    for (int q = 0; q < 4; q++) acc[mb][o][q] = 0.f;
            {
                uint32_t aH_[2] = {aH0[cur][0], aH0[cur][1]};
                uint32_t aL_[2] = {aL0[cur][0], aL0[cur][1]};
                uint32_t bH_[2] = {b1H[0], b1H[1]}, bL_[2] = {b1L[0], b1L[1]};
#pragma unroll
                for (int kk = 0; kk < 8; kk++) {
                    uint32_t ah[2][4], al[2][4], bb[2][4];
                    ldsm_x4(ah[0], aH_[0]); ldsm_x4(ah[1], aH_[1]);
                    ldsm_x4(al[0], aL_[0]); ldsm_x4(al[1], aL_[1]);
                    ldsm_x4(bb[0], bH_[0]); ldsm_x4(bb[1], bH_[1]);
#pragma unroll
                    for (int mb = 0; mb < 2; mb++)
#pragma unroll
                        for (int o = 0; o < 4; o++) {
                            const uint32_t* b = &bb[o >> 1][(o & 1) * 2];
                            mma_bf16(acc[mb][o], ah[mb], b);
                            mma_bf16(acc[mb][o], al[mb], b);
                        }
                    ldsm_x4(bb[0], bL_[0]); ldsm_x4(bb[1], bL_[1]);
#pragma unroll
                    for (int mb = 0; mb < 2; mb++)
#pragma unroll
                        for (int o = 0; o < 4; o++)
                            mma_bf16(acc[mb][o], ah[mb], &bb[o >> 1][(o & 1) * 2]);
#pragma unroll
                    for (int i = 0; i < 2; i++) {
                        aH_[i] += 32; aL_[i] += 32; bH_[i] += 32; bL_[i] += 32;
                    }
                }
            }
            BAR_CONS();   // all consumers done reading A[cur]

            // ---- h1 = relu(acc + b1), split-pack into A[cur] ----
            {
                const uint32_t ahb = AH[cur], alb = AL[cur];
#pragma unroll
                for (int mb = 0; mb < 2; mb++) {
                    const int r0 = m0 + mb * 16 + (lane >> 2);
#pragma unroll
                    for (int o = 0; o < 4; o++) {
                        const int col = n0 + o * 8 + (lane & 3) * 2;
                        const float c0 = bs1[col], c1 = bs1[col + 1];
                        const uint32_t off0 = (uint32_t)(r0 * SAB + col) * 2;
                        const uint32_t off8 = (uint32_t)((r0 + 8) * SAB + col) * 2;
                        float v0 = fmaxf(acc[mb][o][0] + c0, 0.f);
                        float v1 = fmaxf(acc[mb][o][1] + c1, 0.f);
                        float h0 = __bfloat162float(__float2bfloat16_rn(v0));
                        float h1 = __bfloat162float(__float2bfloat16_rn(v1));
                        *(uint32_t*)(smem + ahb + off0) = pack_bf16(h0, h1);
                        *(uint32_t*)(smem + alb + off0) = pack_bf16(v0 - h0, v1 - h1);
                        float v2 = fmaxf(acc[mb][o][2] + c0, 0.f);
                        float v3 = fmaxf(acc[mb][o][3] + c1, 0.f);
                        float h2 = __bfloat162float(__float2bfloat16_rn(v2));
                        float h3 = __bfloat162float(__float2bfloat16_rn(v3));
                        *(uint32_t*)(smem + ahb + off8) = pack_bf16(h2, h3);
                        *(uint32_t*)(smem + alb + off8) = pack_bf16(v2 - h2, v3 - h3);
                    }
                }
            }
            BAR_CONS();

            // ================= GEMM2: acc = h1 @ W2^T =================
#pragma unroll
            for (int mb = 0; mb < 2; mb++)
#pragma unroll
                for (int o = 0; o < 4; o++)
#pragma unroll
                    for (int q = 0; q < 4; q++) acc[mb][o][q] = 0.f;
            {
                uint32_t aH_[2] = {aH0[cur][0], aH0[cur][1]};
                uint32_t aL_[2] = {aL0[cur][0], aL0[cur][1]};
                uint32_t bH_[2] = {b2H[0], b2H[1]}, bL_[2] = {b2L[0], b2L[1]};
#pragma unroll
                for (int kk = 0; kk < 8; kk++) {
                    uint32_t ah[2][4], al[2][4], bb[2][4];
                    ldsm_x4(ah[0], aH_[0]); ldsm_x4(ah[1], aH_[1]);
                    ldsm_x4(al[0], aL_[0]); ldsm_x4(al[1], aL_[1]);
                    ldsm_x4(bb[0], bH_[0]); ldsm_x4(bb[1], bH_[1]);
#pragma unroll
                    for (int mb = 0; mb < 2; mb++)
#pragma unroll
                        for (int o = 0; o < 4; o++) {
                            const uint32_t* b = &bb[o >> 1][(o & 1) * 2];
                            mma_bf16(acc[mb][o], ah[mb], b);
                            mma_bf16(acc[mb][o], al[mb], b);
                        }
                    ldsm_x4(bb[0], bL_[0]); ldsm_x4(bb[1], bL_[1]);
#pragma unroll
                    for (int mb = 0; mb < 2; mb++)
#pragma unroll
                        for (int o = 0; o < 4; o++)
                            mma_bf16(acc[mb][o], ah[mb], &bb[o >> 1][(o & 1) * 2]);
#pragma unroll
                    for (int i = 0; i < 2; i++) {
                        aH_[i] += 32; aL_[i] += 32; bH_[i] += 32; bL_[i] += 32;
                    }
                }
            }

            // ---- final epilogue: relu(acc + b2) -> C ----
#pragma unroll
            for (int mb = 0; mb < 2; mb++) {
                const int rbase = row0 + m0 + mb * 16 + (lane >> 2);
#pragma unroll
                for (int o = 0; o < 4; o++) {
                    const int col = n0 + o * 8 + (lane & 3) * 2;
                    const float c0 = bs2[col], c1 = bs2[col + 1];
                    if (rbase < M) {
                        float2 v = make_float2(fmaxf(acc[mb][o][0] + c0, 0.f),
                                               fmaxf(acc[mb][o][1] + c1, 0.f));
                        *(float2*)(C + (size_t)rbase * FEAT + col) = v;
                    }
                    if (rbase + 8 < M) {
                        float2 v = make_float2(fmaxf(acc[mb][o][2] + c0, 0.f),
                                               fmaxf(acc[mb][o][3] + c1, 0.f));
                        *(float2*)(C + (size_t)(rbase + 8) * FEAT + col) = v;
                    }
                }
            }
        }
        __syncthreads();   // buffer swap point: producers' fill & consumers' reads done
    }
}

// ===========================================================================
// Global mean pool per graph (batch sorted -> binary search)
// ===========================================================================
__global__ void pool_kernel(const float* __restrict__ h, const void* __restrict__ batch,
                            float* __restrict__ out_pool) {
    const int g = blockIdx.x;
    const int c = threadIdx.x;
    const int is64 = g_idx64;
    const long long* b64 = (const long long*)batch;
    const int* b32 = (const int*)batch;

    int lo = 0, hi = N_NODES;
    while (lo < hi) {
        int mid = (lo + hi) >> 1;
        long long v = is64 ? b64[mid] : (long long)b32[mid];
        if (v < (long long)g) lo = mid + 1; else hi = mid;
    }
    const int start = lo;
    hi = N_NODES;
    while (lo < hi) {
        int mid = (lo + hi) >> 1;
        long long v = is64 ? b64[mid] : (long long)b32[mid];
        if (v < (long long)g + 1) lo = mid + 1; else hi = mid;
    }
    const int end = lo;

    float s = 0.f;
    for (int r = start; r < end; r++) s += h[(size_t)r * FEAT + c];
    out_pool[g * FEAT + c] = s / fmaxf((float)(end - start), 1.f);
}

// ===========================================================================
extern "C" void kernel_launch(void* const* d_in, const int* in_sizes, int n_in,
                              void* d_out, int out_size) {
    const float* x   = (const float*)d_in[0];
    const void*  ei  = d_in[1];
    const void*  bat = d_in[2];
    const float* W1 = (const float*)d_in[3];
    const float* b1 = (const float*)d_in[4];
    const float* W2 = (const float*)d_in[5];
    const float* b2 = (const float*)d_in[6];
    const float* W3 = (const float*)d_in[7];
    const float* b3 = (const float*)d_in[8];
    const float* W4 = (const float*)d_in[9];
    const float* b4 = (const float*)d_in[10];

    float* out      = (float*)d_out;
    float* out_pool = out;
    float* out_h    = out + N_GRAPHS * FEAT;

    float* bufB;
    int *deg, *rowptr, *cursor, *csrsrc, *blocksum, *blockoff;
    cudaGetSymbolAddress((void**)&bufB, g_bufB);
    cudaGetSymbolAddress((void**)&deg, g_deg);
    cudaGetSymbolAddress((void**)&rowptr, g_rowptr);
    cudaGetSymbolAddress((void**)&cursor, g_cursor);
    cudaGetSymbolAddress((void**)&csrsrc, g_csrsrc);
    cudaGetSymbolAddress((void**)&blocksum, g_blocksum);
    cudaGetSymbolAddress((void**)&blockoff, g_blockoff);

    cudaFuncSetAttribute(gin_layer_kernel,
                         cudaFuncAttributeMaxDynamicSharedMemorySize, SMF_TOTAL);

    const int edge_blocks = (N_EDGES + 255) / 256;

    // ---- CSR build ----
    detect_kernel<<<1, 32>>>((const int*)ei);
    cudaMemsetAsync(deg, 0, N_NODES * sizeof(int));
    hist_kernel<<<edge_blocks, 256>>>(ei, deg);
    scanA_kernel<<<SCAN_BLOCKS, 256>>>(deg, blocksum);
    scanB_kernel<<<1, 128>>>(blocksum, blockoff, rowptr);
    scanC_kernel<<<SCAN_BLOCKS, 256>>>(deg, blockoff, rowptr, cursor);
    fill_kernel<<<edge_blocks, 256>>>(ei, cursor, csrsrc);

    // ---- Layer 1 (fused agg + MLP) ----
    gin_layer_kernel<<<GEMM_GRID, 512, SMF_TOTAL>>>(x, W1, b1, W2, b2, bufB, N_NODES,
                                                    rowptr, csrsrc);
    // ---- Layer 2 ----
    gin_layer_kernel<<<GEMM_GRID, 512, SMF_TOTAL>>>(bufB, W3, b3, W4, b4, out_h, N_NODES,
                                                    rowptr, csrsrc);

    // ---- Global mean pool ----
    pool_kernel<<<N_GRAPHS, FEAT>>>(out_h, bat, out_pool);
}

// round 12
// speedup vs baseline: 1.7001x; 1.7001x over previous
#include <cuda_runtime.h>
#include <cuda_bf16.h>
#include <cstdint>

#define N_NODES 100000
#define N_EDGES 1600000
#define FEAT 128
#define N_GRAPHS 100

#define CHROWS 6272                 // 98*64 rows per progress chunk
#define NCHP 16                     // ceil(100000/6272)
#define AGG_BLOCKS ((N_NODES + 7) / 8)   // 12500, 8 nodes per 256-thr block

#define SCAN_ITEMS 1024
#define SCAN_BLOCKS ((N_NODES + SCAN_ITEMS - 1) / SCAN_ITEMS)  // 98

// Scratch (allocation-free rule: __device__ globals)
__device__ float    g_bufB[(size_t)N_NODES * FEAT];
__device__ uint32_t g_hi[(size_t)N_NODES * 64];
__device__ uint32_t g_lo[(size_t)N_NODES * 64];
__device__ int   g_deg[N_NODES];
__device__ int   g_rowptr[N_NODES + 1];
__device__ int   g_cursor[N_NODES];
__device__ int   g_csrsrc[N_EDGES];
__device__ int   g_blocksum[SCAN_BLOCKS];
__device__ int   g_blockoff[SCAN_BLOCKS];
__device__ int   g_cnt[2][NCHP];    // per-layer chunk counters
__device__ int   g_flag[2][NCHP];   // per-layer chunk ready flags
__device__ int   g_idx64;

// ===========================================================================
// Helpers
// ===========================================================================
__device__ __forceinline__ uint32_t smem_u32(const void* p) {
    uint32_t a;
    asm("{ .reg .u64 t; cvta.to.shared.u64 t, %1; cvt.u32.u64 %0, t; }" : "=r"(a) : "l"(p));
    return a;
}
__device__ __forceinline__ uint32_t pack_bf16(float a, float b) {  // {lo=a, hi=b}
    uint32_t r;
    asm("cvt.rn.bf16x2.f32 %0, %1, %2;" : "=r"(r) : "f"(b), "f"(a));
    return r;
}
__device__ __forceinline__ void ldsm_x4(uint32_t* r, uint32_t addr) {
    asm volatile("ldmatrix.sync.aligned.m8n8.x4.shared.b16 {%0,%1,%2,%3}, [%4];"
        : "=r"(r[0]), "=r"(r[1]), "=r"(r[2]), "=r"(r[3]) : "r"(addr));
}
__device__ __forceinline__ void mma_bf16(float* c, const uint32_t* a, const uint32_t* b) {
    asm volatile("mma.sync.aligned.m16n8k16.row.col.f32.bf16.bf16.f32 "
        "{%0,%1,%2,%3}, {%4,%5,%6,%7}, {%8,%9}, {%0,%1,%2,%3};"
        : "+f"(c[0]), "+f"(c[1]), "+f"(c[2]), "+f"(c[3])
        : "r"(a[0]), "r"(a[1]), "r"(a[2]), "r"(a[3]), "r"(b[0]), "r"(b[1]));
}
__device__ __forceinline__ void cp16(uint32_t saddr, const void* gptr) {
    asm volatile("cp.async.cg.shared.global [%0], [%1], 16;" :: "r"(saddr), "l"(gptr));
}
#define CP_COMMIT() asm volatile("cp.async.commit_group;" ::: "memory")
#define CP_WAIT0()  asm volatile("cp.async.wait_group 0;" ::: "memory")

// ===========================================================================
// Index dtype detector
// ===========================================================================
__global__ void detect_kernel(const int* __restrict__ ei_words) {
    const int lane = threadIdx.x;
    int ok = 1;
#pragma unroll
    for (int j = 0; j < 16; j++) {
        int i = j * 32 + lane;
        int lo = ei_words[2 * i];
        int hi = ei_words[2 * i + 1];
        if (hi != 0 || lo < 0 || lo >= N_NODES) ok = 0;
    }
    int all = __all_sync(0xffffffffu, ok);
    if (lane == 0) g_idx64 = all;
}
__device__ __forceinline__ int load_idx(const void* p, long long i) {
    return g_idx64 ? (int)((const long long*)p)[i] : ((const int*)p)[i];
}

// ===========================================================================
// CSR build
// ===========================================================================
__global__ void hist_kernel(const void* __restrict__ ei, int* __restrict__ deg) {
    int e = blockIdx.x * blockDim.x + threadIdx.x;
    if (e >= N_EDGES) return;
    atomicAdd(&deg[load_idx(ei, (long long)N_EDGES + e)], 1);
}
__global__ void scanA_kernel(const int* __restrict__ deg, int* __restrict__ blocksum) {
    __shared__ int red[256];
    const int t = threadIdx.x;
    const int base = blockIdx.x * SCAN_ITEMS;
    int s = 0;
#pragma unroll
    for (int j = 0; j < 4; j++) {
        int i = base + t + j * 256;
        if (i < N_NODES) s += deg[i];
    }
    red[t] = s;
    __syncthreads();
    for (int off = 128; off > 0; off >>= 1) {
        if (t < off) red[t] += red[t + off];
        __syncthreads();
    }
    if (t == 0) blocksum[blockIdx.x] = red[0];
}
__global__ void scanB_kernel(const int* __restrict__ blocksum,
                             int* __restrict__ blockoff, int* __restrict__ rowptr) {
    __shared__ int v[128];
    const int t = threadIdx.x;
    v[t] = (t < SCAN_BLOCKS) ? blocksum[t] : 0;
    __syncthreads();
    int mine = v[t];
    for (int off = 1; off < 128; off <<= 1) {
        int tmp = (t >= off) ? v[t - off] : 0;
        __syncthreads();
        v[t] += tmp;
        __syncthreads();
    }
    if (t < SCAN_BLOCKS) blockoff[t] = v[t] - mine;
    if (t == 127) rowptr[N_NODES] = v[127];
}
__global__ void scanC_kernel(const int* __restrict__ deg, const int* __restrict__ blockoff,
                             int* __restrict__ rowptr, int* __restrict__ cursor) {
    __shared__ int ts[256];
    const int t = threadIdx.x;
    const int base = blockIdx.x * SCAN_ITEMS + t * 4;
    int d0 = 0, d1 = 0, d2 = 0, d3 = 0;
    if (base + 0 < N_NODES) d0 = deg[base + 0];
    if (base + 1 < N_NODES) d1 = deg[base + 1];
    if (base + 2 < N_NODES) d2 = deg[base + 2];
    if (base + 3 < N_NODES) d3 = deg[base + 3];
    int tot = d0 + d1 + d2 + d3;
    ts[t] = tot;
    __syncthreads();
    for (int off = 1; off < 256; off <<= 1) {
        int tmp = (t >= off) ? ts[t - off] : 0;
        __syncthreads();
        ts[t] += tmp;
        __syncthreads();
    }
    int run = blockoff[blockIdx.x] + ts[t] - tot;
    if (base + 0 < N_NODES) { rowptr[base + 0] = run; cursor[base + 0] = run; run += d0; }
    if (base + 1 < N_NODES) { rowptr[base + 1] = run; cursor[base + 1] = run; run += d1; }
    if (base + 2 < N_NODES) { rowptr[base + 2] = run; cursor[base + 2] = run; run += d2; }
    if (base + 3 < N_NODES) { rowptr[base + 3] = run; cursor[base + 3] = run; run += d3; }
}
__global__ void fill_kernel(const void* __restrict__ ei,
                            int* __restrict__ cursor, int* __restrict__ csrsrc) {
    int e = blockIdx.x * blockDim.x + threadIdx.x;
    if (e >= N_EDGES) return;
    int s = load_idx(ei, e);
    int d = load_idx(ei, (long long)N_EDGES + e);
    csrsrc[atomicAdd(&cursor[d], 1)] = s;
}

// ===========================================================================
// GIN aggregation (gather) with per-chunk completion signaling.
// Block b handles nodes [8b, 8b+8). Emits bf16 (hi,lo) split words.
// ===========================================================================
__global__ void __launch_bounds__(256)
agg_kernel(const float* __restrict__ x,
           uint32_t* __restrict__ hi, uint32_t* __restrict__ lo,
           const int* __restrict__ rowptr, const int* __restrict__ csrsrc,
           int* __restrict__ cnt, int* __restrict__ flag) {
    const int n = blockIdx.x * 8 + (threadIdx.x >> 5);
    const int lane = threadIdx.x & 31;
    if (n < N_NODES) {
        const int beg = rowptr[n];
        const int end = rowptr[n + 1];
        float4 acc = ((const float4*)(x + (size_t)n * FEAT))[lane];
        for (int base = beg; base < end; base += 32) {
            const int cnt_e = min(32, end - base);
            int sid = (base + lane < end) ? csrsrc[base + lane] : 0;
#pragma unroll 4
            for (int j = 0; j < cnt_e; j++) {
                int s = __shfl_sync(0xffffffffu, sid, j);
                float4 v = ((const float4*)(x + (size_t)s * FEAT))[lane];
                acc.x += v.x; acc.y += v.y; acc.z += v.z; acc.w += v.w;
            }
        }
        float h0 = __bfloat162float(__float2bfloat16_rn(acc.x));
        float h1 = __bfloat162float(__float2bfloat16_rn(acc.y));
        float h2 = __bfloat162float(__float2bfloat16_rn(acc.z));
        float h3 = __bfloat162float(__float2bfloat16_rn(acc.w));
        ((uint2*)(hi + (size_t)n * 64))[lane] = make_uint2(pack_bf16(h0, h1), pack_bf16(h2, h3));
        ((uint2*)(lo + (size_t)n * 64))[lane] =
            make_uint2(pack_bf16(acc.x - h0, acc.y - h1), pack_bf16(acc.z - h2, acc.w - h3));
    }
    __syncthreads();
    if (threadIdx.x == 0) {
        __threadfence();
        const int c = (blockIdx.x * 8) / CHROWS;
        const int rows_c = min(CHROWS, N_NODES - c * CHROWS);
        const int expected = (rows_c + 7) >> 3;
        if (atomicAdd(&cnt[c], 1) + 1 == expected)
            atomicExch(&flag[c], 1);
    }
}

// ===========================================================================
// Fused persistent MLP (two bf16-split HMMA GEMMs), progress-gated on agg.
// ===========================================================================
#define SAB 136
#define WTILE_B (128 * SAB * 2)
#define ATILE_B (64 * SAB * 2)
#define SMF_B1   0
#define SMF_B2   512
#define SMF_W1H  1024
#define SMF_W1L  (SMF_W1H + WTILE_B)
#define SMF_W2H  (SMF_W1H + 2 * WTILE_B)
#define SMF_W2L  (SMF_W1H + 3 * WTILE_B)
#define SMF_A0H  (SMF_W1H + 4 * WTILE_B)
#define SMF_A0L  (SMF_A0H + ATILE_B)
#define SMF_A1H  (SMF_A0H + 2 * ATILE_B)
#define SMF_A1L  (SMF_A0H + 3 * ATILE_B)
#define SMF_TOTAL (SMF_A0H + 4 * ATILE_B)  // 209920
#define GEMM_GRID 148

__device__ __forceinline__ void wait_chunk(int* flag, int row0) {
    const int c = row0 / CHROWS;
    if (threadIdx.x == 0) {
        while (atomicAdd(flag + c, 0) == 0) __nanosleep(256);
        __threadfence();
    }
    __syncthreads();
}

__device__ __forceinline__ void prefetch_tile(uint32_t sb, uint32_t ah, uint32_t al,
                                              const uint32_t* hi, const uint32_t* lo,
                                              int row0, int M, int tid) {
#pragma unroll
    for (int j = 0; j < 4; j++) {
        const int i = tid + j * 256;
        const int r = i >> 4, c = i & 15;
        if (row0 + r < M) {
            const uint32_t so = (uint32_t)(r * SAB + c * 8) * 2;
            cp16(sb + ah + so, hi + (size_t)(row0 + r) * 64 + c * 4);
            cp16(sb + al + so, lo + (size_t)(row0 + r) * 64 + c * 4);
        }
    }
    CP_COMMIT();
}

__global__ void __launch_bounds__(256, 2)
mlp_fused_kernel(const uint32_t* __restrict__ Ahi, const uint32_t* __restrict__ Alo,
                 const float* __restrict__ W1, const float* __restrict__ b1,
                 const float* __restrict__ W2, const float* __restrict__ b2,
                 float* __restrict__ C, int M, int* __restrict__ flag) {
    extern __shared__ char smem[];
    const uint32_t sb = smem_u32(smem);
    const int tid = threadIdx.x;
    const int lane = tid & 31;
    const int wid = tid >> 5;
    const int numTiles = (M + 63) >> 6;

    const uint32_t AH[2] = {SMF_A0H, SMF_A1H};
    const uint32_t AL[2] = {SMF_A0L, SMF_A1L};

    // ---- biases + one-time W1/W2 split-convert (overlaps agg startup) ----
    if (tid < 128) ((float*)(smem + SMF_B1))[tid] = b1[tid];
    else           ((float*)(smem + SMF_B2))[tid - 128] = b2[tid - 128];
    {
        const int r = tid >> 1;
        const int half = tid & 1;
        const float4* w1row = (const float4*)(W1 + (size_t)r * FEAT);
        const float4* w2row = (const float4*)(W2 + (size_t)r * FEAT);
#pragma unroll
        for (int j = 0; j < 16; j++) {
            const int col = half * 64 + j * 4;
            const uint32_t off = (uint32_t)(r * SAB + col) * 2;
            float4 v1 = w1row[half * 16 + j];
            float a0 = __bfloat162float(__float2bfloat16_rn(v1.x));
            float a1 = __bfloat162float(__float2bfloat16_rn(v1.y));
            float a2 = __bfloat162float(__float2bfloat16_rn(v1.z));
            float a3 = __bfloat162float(__float2bfloat16_rn(v1.w));
            *(uint2*)(smem + SMF_W1H + off) = make_uint2(pack_bf16(a0, a1), pack_bf16(a2, a3));
            *(uint2*)(smem + SMF_W1L + off) =
                make_uint2(pack_bf16(v1.x - a0, v1.y - a1), pack_bf16(v1.z - a2, v1.w - a3));
            float4 v2 = w2row[half * 16 + j];
            float c0 = __bfloat162float(__float2bfloat16_rn(v2.x));
            float c1 = __bfloat162float(__float2bfloat16_rn(v2.y));
            float c2 = __bfloat162float(__float2bfloat16_rn(v2.z));
            float c3 = __bfloat162float(__float2bfloat16_rn(v2.w));
            *(uint2*)(smem + SMF_W2H + off) = make_uint2(pack_bf16(c0, c1), pack_bf16(c2, c3));
            *(uint2*)(smem + SMF_W2L + off) =
                make_uint2(pack_bf16(v2.x - c0, v2.y - c1), pack_bf16(v2.z - c2, v2.w - c3));
        }
    }

    // ---- gated prefetch of first A tile into buffer 0 ----
    int tile = blockIdx.x;
    if (tile < numTiles) {
        wait_chunk(flag, tile << 6);
        prefetch_tile(sb, AH[0], AL[0], Ahi, Alo, tile << 6, M, tid);
    } else {
        CP_COMMIT();
    }

    // ---- warp tiling constants ----
    const int m0 = (wid & 1) * 32;
    const int n0 = (wid >> 1) * 32;
    const int g = lane >> 3, rr = lane & 7;
    uint32_t aH0[2][2], aL0[2][2], b1H[2], b1L[2], b2H[2], b2L[2];
#pragma unroll
    for (int b = 0; b < 2; b++)
#pragma unroll
        for (int mb = 0; mb < 2; mb++) {
            const uint32_t o =
                (uint32_t)((m0 + mb * 16 + (g & 1) * 8 + rr) * SAB + (g >> 1) * 8) * 2;
            aH0[b][mb] = sb + AH[b] + o;
            aL0[b][mb] = sb + AL[b] + o;
        }
#pragma unroll
    for (int p = 0; p < 2; p++) {
        const uint32_t o = (uint32_t)((n0 + p * 16 + (g >> 1) * 8 + rr) * SAB + (g & 1) * 8) * 2;
        b1H[p] = sb + SMF_W1H + o;
        b1L[p] = sb + SMF_W1L + o;
        b2H[p] = sb + SMF_W2H + o;
        b2L[p] = sb + SMF_W2L + o;
    }
    const float* bs1 = (const float*)(smem + SMF_B1);
    const float* bs2 = (const float*)(smem + SMF_B2);

    // ---- persistent tile loop (double-buffered A) ----
    int cur = 0;
    for (; tile < numTiles; tile += GEMM_GRID, cur ^= 1) {
        const int row0 = tile << 6;

        CP_WAIT0();
        __syncthreads();

        // gated prefetch of next tile (overlaps both GEMMs)
        const int nt = tile + GEMM_GRID;
        if (nt < numTiles) {
            wait_chunk(flag, nt << 6);
            prefetch_tile(sb, AH[cur ^ 1], AL[cur ^ 1], Ahi, Alo, nt << 6, M, tid);
        } else {
            CP_COMMIT();
        }

        // ================= GEMM1: acc = A @ W1^T =================
        float acc[2][4][4];
#pragma unroll
        for (int mb = 0; mb < 2; mb++)
#pragma unroll
            for (int o = 0; o < 4; o++)
#pragma unroll
                for (int q = 0; q < 4; q++) acc[mb][o][q] = 0.f;
        {
            uint32_t aH_[2] = {aH0[cur][0], aH0[cur][1]}, aL_[2] = {aL0[cur][0], aL0[cur][1]};
            uint32_t bH_[2] = {b1H[0], b1H[1]}, bL_[2] = {b1L[0], b1L[1]};
#pragma unroll
            for (int kk = 0; kk < 8; kk++) {
                uint32_t ah[2][4], al[2][4], bb[2][4];
                ldsm_x4(ah[0], aH_[0]); ldsm_x4(ah[1], aH_[1]);
                ldsm_x4(al[0], aL_[0]); ldsm_x4(al[1], aL_[1]);
                ldsm_x4(bb[0], bH_[0]); ldsm_x4(bb[1], bH_[1]);
#pragma unroll
                for (int mb = 0; mb < 2; mb++)
#pragma unroll
                    for (int o = 0; o < 4; o++) {
                        const uint32_t* b = &bb[o >> 1][(o & 1) * 2];
                        mma_bf16(acc[mb][o], ah[mb], b);
                        mma_bf16(acc[mb][o], al[mb], b);
                    }
                ldsm_x4(bb[0], bL_[0]); ldsm_x4(bb[1], bL_[1]);
#pragma unroll
                for (int mb = 0; mb < 2; mb++)
#pragma unroll
                    for (int o = 0; o < 4; o++)
                        mma_bf16(acc[mb][o], ah[mb], &bb[o >> 1][(o & 1) * 2]);
#pragma unroll
                for (int i = 0; i < 2; i++) { aH_[i] += 32; aL_[i] += 32; bH_[i] += 32; bL_[i] += 32; }
            }
        }
        __syncthreads();

        // ---- h1 = relu(acc + b1), split-pack into A[cur] ----
        {
            const uint32_t ahb = AH[cur], alb = AL[cur];
#pragma unroll
            for (int mb = 0; mb < 2; mb++) {
                const int r0 = m0 + mb * 16 + (lane >> 2);
#pragma unroll
                for (int o = 0; o < 4; o++) {
                    const int col = n0 + o * 8 + (lane & 3) * 2;
                    const float c0 = bs1[col], c1 = bs1[col + 1];
                    const uint32_t off0 = (uint32_t)(r0 * SAB + col) * 2;
                    const uint32_t off8 = (uint32_t)((r0 + 8) * SAB + col) * 2;
                    float v0 = fmaxf(acc[mb][o][0] + c0, 0.f);
                    float v1 = fmaxf(acc[mb][o][1] + c1, 0.f);
                    float h0 = __bfloat162float(__float2bfloat16_rn(v0));
                    float h1 = __bfloat162float(__float2bfloat16_rn(v1));
                    *(uint32_t*)(smem + ahb + off0) = pack_bf16(h0, h1);
                    *(uint32_t*)(smem + alb + off0) = pack_bf16(v0 - h0, v1 - h1);
                    float v2 = fmaxf(acc[mb][o][2] + c0, 0.f);
                    float v3 = fmaxf(acc[mb][o][3] + c1, 0.f);
                    float h2 = __bfloat162float(__float2bfloat16_rn(v2));
                    float h3 = __bfloat162float(__float2bfloat16_rn(v3));
                    *(uint32_t*)(smem + ahb + off8) = pack_bf16(h2, h3);
                    *(uint32_t*)(smem + alb + off8) = pack_bf16(v2 - h2, v3 - h3);
                }
            }
        }
        __syncthreads();

        // ================= GEMM2: acc = h1 @ W2^T =================
#pragma unroll
        for (int mb = 0; mb < 2; mb++)
#pragma unroll
            for (int o = 0; o < 4; o++)
#pragma unroll
                for (int q = 0; q < 4; q++) acc[mb][o][q] = 0.f;
        {
            uint32_t aH_[2] = {aH0[cur][0], aH0[cur][1]}, aL_[2] = {aL0[cur][0], aL0[cur][1]};
            uint32_t bH_[2] = {b2H[0], b2H[1]}, bL_[2] = {b2L[0], b2L[1]};
#pragma unroll
            for (int kk = 0; kk < 8; kk++) {
                uint32_t ah[2][4], al[2][4], bb[2][4];
                ldsm_x4(ah[0], aH_[0]); ldsm_x4(ah[1], aH_[1]);
                ldsm_x4(al[0], aL_[0]); ldsm_x4(al[1], aL_[1]);
                ldsm_x4(bb[0], bH_[0]); ldsm_x4(bb[1], bH_[1]);
#pragma unroll
                for (int mb = 0; mb < 2; mb++)
#pragma unroll
                    for (int o = 0; o < 4; o++) {
                        const uint32_t* b = &bb[o >> 1][(o & 1) * 2];
                        mma_bf16(acc[mb][o], ah[mb], b);
                        mma_bf16(acc[mb][o], al[mb], b);
                    }
                ldsm_x4(bb[0], bL_[0]); ldsm_x4(bb[1], bL_[1]);
#pragma unroll
                for (int mb = 0; mb < 2; mb++)
#pragma unroll
                    for (int o = 0; o < 4; o++)
                        mma_bf16(acc[mb][o], ah[mb], &bb[o >> 1][(o & 1) * 2]);
#pragma unroll
                for (int i = 0; i < 2; i++) { aH_[i] += 32; aL_[i] += 32; bH_[i] += 32; bL_[i] += 32; }
            }
        }

        // ---- final epilogue: relu(acc + b2) -> C ----
#pragma unroll
        for (int mb = 0; mb < 2; mb++) {
            const int rbase = row0 + m0 + mb * 16 + (lane >> 2);
#pragma unroll
            for (int o = 0; o < 4; o++) {
                const int col = n0 + o * 8 + (lane & 3) * 2;
                const float c0 = bs2[col], c1 = bs2[col + 1];
                if (rbase < M) {
                    float2 v = make_float2(fmaxf(acc[mb][o][0] + c0, 0.f),
                                           fmaxf(acc[mb][o][1] + c1, 0.f));
                    *(float2*)(C + (size_t)rbase * FEAT + col) = v;
                }
                if (rbase + 8 < M) {
                    float2 v = make_float2(fmaxf(acc[mb][o][2] + c0, 0.f),
                                           fmaxf(acc[mb][o][3] + c1, 0.f));
                    *(float2*)(C + (size_t)(rbase + 8) * FEAT + col) = v;
                }
            }
        }
    }
}

// ===========================================================================
// Global mean pool per graph (batch sorted -> binary search)
// ===========================================================================
__global__ void pool_kernel(const float* __restrict__ h, const void* __restrict__ batch,
                            float* __restrict__ out_pool) {
    const int g = blockIdx.x;
    const int c = threadIdx.x;
    const int is64 = g_idx64;
    const long long* b64 = (const long long*)batch;
    const int* b32 = (const int*)batch;

    int lo = 0, hi = N_NODES;
    while (lo < hi) {
        int mid = (lo + hi) >> 1;
        long long v = is64 ? b64[mid] : (long long)b32[mid];
        if (v < (long long)g) lo = mid + 1; else hi = mid;
    }
    const int start = lo;
    hi = N_NODES;
    while (lo < hi) {
        int mid = (lo + hi) >> 1;
        long long v = is64 ? b64[mid] : (long long)b32[mid];
        if (v < (long long)g + 1) lo = mid + 1; else hi = mid;
    }
    const int end = lo;

    float s = 0.f;
    for (int r = start; r < end; r++) s += h[(size_t)r * FEAT + c];
    out_pool[g * FEAT + c] = s / fmaxf((float)(end - start), 1.f);
}

// ===========================================================================
extern "C" void kernel_launch(void* const* d_in, const int* in_sizes, int n_in,
                              void* d_out, int out_size) {
    const float* x   = (const float*)d_in[0];
    const void*  ei  = d_in[1];
    const void*  bat = d_in[2];
    const float* W1 = (const float*)d_in[3];
    const float* b1 = (const float*)d_in[4];
    const float* W2 = (const float*)d_in[5];
    const float* b2 = (const float*)d_in[6];
    const float* W3 = (const float*)d_in[7];
    const float* b3 = (const float*)d_in[8];
    const float* W4 = (const float*)d_in[9];
    const float* b4 = (const float*)d_in[10];

    float* out      = (float*)d_out;
    float* out_pool = out;
    float* out_h    = out + N_GRAPHS * FEAT;

    float* bufB;
    uint32_t *hi, *lo;
    int *deg, *rowptr, *cursor, *csrsrc, *blocksum, *blockoff, *cntArr, *flagArr;
    cudaGetSymbolAddress((void**)&bufB, g_bufB);
    cudaGetSymbolAddress((void**)&hi, g_hi);
    cudaGetSymbolAddress((void**)&lo, g_lo);
    cudaGetSymbolAddress((void**)&deg, g_deg);
    cudaGetSymbolAddress((void**)&rowptr, g_rowptr);
    cudaGetSymbolAddress((void**)&cursor, g_cursor);
    cudaGetSymbolAddress((void**)&csrsrc, g_csrsrc);
    cudaGetSymbolAddress((void**)&blocksum, g_blocksum);
    cudaGetSymbolAddress((void**)&blockoff, g_blockoff);
    cudaGetSymbolAddress((void**)&cntArr, g_cnt);
    cudaGetSymbolAddress((void**)&flagArr, g_flag);

    cudaFuncSetAttribute(mlp_fused_kernel,
                         cudaFuncAttributeMaxDynamicSharedMemorySize, SMF_TOTAL);

    // ---- lazy one-time stream/event handles ----
    static cudaStream_t sA = nullptr, sM = nullptr;
    static cudaEvent_t evCSR, evM1, evFinal, evAend;
    if (sA == nullptr) {
        int loPri, hiPri;
        cudaDeviceGetStreamPriorityRange(&loPri, &hiPri);
        cudaStreamCreateWithPriority(&sA, cudaStreamNonBlocking, hiPri);  // agg: highest
        cudaStreamCreateWithPriority(&sM, cudaStreamNonBlocking, loPri);
        cudaEventCreateWithFlags(&evCSR, cudaEventDisableTiming);
        cudaEventCreateWithFlags(&evM1, cudaEventDisableTiming);
        cudaEventCreateWithFlags(&evFinal, cudaEventDisableTiming);
        cudaEventCreateWithFlags(&evAend, cudaEventDisableTiming);
    }

    const int edge_blocks = (N_EDGES + 255) / 256;

    // ---- CSR build + sync-state zeroing on main stream ----
    detect_kernel<<<1, 32>>>((const int*)ei);
    cudaMemsetAsync(deg, 0, N_NODES * sizeof(int));
    cudaMemsetAsync(cntArr, 0, 2 * NCHP * sizeof(int));
    cudaMemsetAsync(flagArr, 0, 2 * NCHP * sizeof(int));
    hist_kernel<<<edge_blocks, 256>>>(ei, deg);
    scanA_kernel<<<SCAN_BLOCKS, 256>>>(deg, blocksum);
    scanB_kernel<<<1, 128>>>(blocksum, blockoff, rowptr);
    scanC_kernel<<<SCAN_BLOCKS, 256>>>(deg, blockoff, rowptr, cursor);
    fill_kernel<<<edge_blocks, 256>>>(ei, cursor, csrsrc);
    cudaEventRecord(evCSR, (cudaStream_t)0);

    // ---- fork: agg on sA (high prio), MLP on sM, progress-gated ----
    cudaStreamWaitEvent(sA, evCSR, 0);
    cudaStreamWaitEvent(sM, evCSR, 0);

    // Layer 1: agg(x -> hi/lo, flags[0]) || mlp(hi/lo -> bufB, gated on flags[0])
    agg_kernel<<<AGG_BLOCKS, 256, 0, sA>>>(x, hi, lo, rowptr, csrsrc,
                                           cntArr + 0, flagArr + 0);
    mlp_fused_kernel<<<GEMM_GRID, 256, SMF_TOTAL, sM>>>(hi, lo, W1, b1, W2, b2,
                                                        bufB, N_NODES, flagArr + 0);
    cudaEventRecord(evM1, sM);

    // Layer 2: agg needs ALL of bufB (waits MLP1); MLP2 gated on flags[1]
    cudaStreamWaitEvent(sA, evM1, 0);
    agg_kernel<<<AGG_BLOCKS, 256, 0, sA>>>(bufB, hi, lo, rowptr, csrsrc,
                                           cntArr + NCHP, flagArr + NCHP);
    cudaEventRecord(evAend, sA);
    mlp_fused_kernel<<<GEMM_GRID, 256, SMF_TOTAL, sM>>>(hi, lo, W3, b3, W4, b4,
                                                        out_h, N_NODES, flagArr + NCHP);

    // ---- pool on sM, then join both branches on main stream ----
    pool_kernel<<<N_GRAPHS, FEAT, 0, sM>>>(out_h, bat, out_pool);
    cudaEventRecord(evFinal, sM);
    cudaStreamWaitEvent((cudaStream_t)0, evFinal, 0);
    cudaStreamWaitEvent((cudaStream_t)0, evAend, 0);
}

// round 14
// speedup vs baseline: 1.8387x; 1.0815x over previous
#include <cuda_runtime.h>
#include <cuda_bf16.h>
#include <cuda_fp16.h>
#include <cstdint>

#define N_NODES 100000
#define N_EDGES 1600000
#define FEAT 128
#define N_GRAPHS 100

#define SCAN_ITEMS 1024
#define SCAN_BLOCKS ((N_NODES + SCAN_ITEMS - 1) / SCAN_ITEMS)  // 98

// Scratch (allocation-free rule: __device__ globals)
__device__ float   g_bufA[(size_t)N_NODES * FEAT];
__device__ float   g_bufB[(size_t)N_NODES * FEAT];
__device__ __half2 g_h16[(size_t)N_NODES * 64];   // fp16 mirror for gathers (256B/row)
__device__ int   g_deg[N_NODES];
__device__ int   g_rowptr[N_NODES + 1];
__device__ int   g_cursor[N_NODES];
__device__ int   g_csrsrc[N_EDGES];
__device__ int   g_blocksum[SCAN_BLOCKS];
__device__ int   g_blockoff[SCAN_BLOCKS];
__device__ int   g_idx64;

// ===========================================================================
// Helpers
// ===========================================================================
__device__ __forceinline__ uint32_t smem_u32(const void* p) {
    uint32_t a;
    asm("{ .reg .u64 t; cvta.to.shared.u64 t, %1; cvt.u32.u64 %0, t; }" : "=r"(a) : "l"(p));
    return a;
}
__device__ __forceinline__ uint32_t pack_bf16(float a, float b) {  // {lo=a, hi=b}
    uint32_t r;
    asm("cvt.rn.bf16x2.f32 %0, %1, %2;" : "=r"(r) : "f"(b), "f"(a));
    return r;
}
__device__ __forceinline__ void ldsm_x4(uint32_t* r, uint32_t addr) {
    asm volatile("ldmatrix.sync.aligned.m8n8.x4.shared.b16 {%0,%1,%2,%3}, [%4];"
        : "=r"(r[0]), "=r"(r[1]), "=r"(r[2]), "=r"(r[3]) : "r"(addr));
}
__device__ __forceinline__ void mma_bf16(float* c, const uint32_t* a, const uint32_t* b) {
    asm volatile("mma.sync.aligned.m16n8k16.row.col.f32.bf16.bf16.f32 "
        "{%0,%1,%2,%3}, {%4,%5,%6,%7}, {%8,%9}, {%0,%1,%2,%3};"
        : "+f"(c[0]), "+f"(c[1]), "+f"(c[2]), "+f"(c[3])
        : "r"(a[0]), "r"(a[1]), "r"(a[2]), "r"(a[3]), "r"(b[0]), "r"(b[1]));
}
__device__ __forceinline__ void cp16(uint32_t saddr, const void* gptr) {
    asm volatile("cp.async.cg.shared.global [%0], [%1], 16;" :: "r"(saddr), "l"(gptr));
}
#define CP_COMMIT() asm volatile("cp.async.commit_group;" ::: "memory")
#define CP_WAIT0()  asm volatile("cp.async.wait_group 0;" ::: "memory")

// ===========================================================================
// Index dtype detector (int64 little-endian => odd words zero). 1 warp.
// ===========================================================================
__global__ void detect_kernel(const int* __restrict__ ei_words) {
    const int lane = threadIdx.x;
    int ok = 1;
#pragma unroll
    for (int j = 0; j < 16; j++) {
        int i = j * 32 + lane;
        int lo = ei_words[2 * i];
        int hi = ei_words[2 * i + 1];
        if (hi != 0 || lo < 0 || lo >= N_NODES) ok = 0;
    }
    int all = __all_sync(0xffffffffu, ok);
    if (lane == 0) g_idx64 = all;
}
__device__ __forceinline__ int load_idx(const void* p, long long i) {
    return g_idx64 ? (int)((const long long*)p)[i] : ((const int*)p)[i];
}

// ===========================================================================
// CSR build
// ===========================================================================
__global__ void hist_kernel(const void* __restrict__ ei, int* __restrict__ deg) {
    int e = blockIdx.x * blockDim.x + threadIdx.x;
    if (e >= N_EDGES) return;
    atomicAdd(&deg[load_idx(ei, (long long)N_EDGES + e)], 1);
}
__global__ void scanA_kernel(const int* __restrict__ deg, int* __restrict__ blocksum) {
    __shared__ int red[256];
    const int t = threadIdx.x;
    const int base = blockIdx.x * SCAN_ITEMS;
    int s = 0;
#pragma unroll
    for (int j = 0; j < 4; j++) {
        int i = base + t + j * 256;
        if (i < N_NODES) s += deg[i];
    }
    red[t] = s;
    __syncthreads();
    for (int off = 128; off > 0; off >>= 1) {
        if (t < off) red[t] += red[t + off];
        __syncthreads();
    }
    if (t == 0) blocksum[blockIdx.x] = red[0];
}
__global__ void scanB_kernel(const int* __restrict__ blocksum,
                             int* __restrict__ blockoff, int* __restrict__ rowptr) {
    __shared__ int v[128];
    const int t = threadIdx.x;
    v[t] = (t < SCAN_BLOCKS) ? blocksum[t] : 0;
    __syncthreads();
    int mine = v[t];
    for (int off = 1; off < 128; off <<= 1) {
        int tmp = (t >= off) ? v[t - off] : 0;
        __syncthreads();
        v[t] += tmp;
        __syncthreads();
    }
    if (t < SCAN_BLOCKS) blockoff[t] = v[t] - mine;
    if (t == 127) rowptr[N_NODES] = v[127];
}
__global__ void scanC_kernel(const int* __restrict__ deg, const int* __restrict__ blockoff,
                             int* __restrict__ rowptr, int* __restrict__ cursor) {
    __shared__ int ts[256];
    const int t = threadIdx.x;
    const int base = blockIdx.x * SCAN_ITEMS + t * 4;
    int d0 = 0, d1 = 0, d2 = 0, d3 = 0;
    if (base + 0 < N_NODES) d0 = deg[base + 0];
    if (base + 1 < N_NODES) d1 = deg[base + 1];
    if (base + 2 < N_NODES) d2 = deg[base + 2];
    if (base + 3 < N_NODES) d3 = deg[base + 3];
    int tot = d0 + d1 + d2 + d3;
    ts[t] = tot;
    __syncthreads();
    for (int off = 1; off < 256; off <<= 1) {
        int tmp = (t >= off) ? ts[t - off] : 0;
        __syncthreads();
        ts[t] += tmp;
        __syncthreads();
    }
    int run = blockoff[blockIdx.x] + ts[t] - tot;
    if (base + 0 < N_NODES) { rowptr[base + 0] = run; cursor[base + 0] = run; run += d0; }
    if (base + 1 < N_NODES) { rowptr[base + 1] = run; cursor[base + 1] = run; run += d1; }
    if (base + 2 < N_NODES) { rowptr[base + 2] = run; cursor[base + 2] = run; run += d2; }
    if (base + 3 < N_NODES) { rowptr[base + 3] = run; cursor[base + 3] = run; run += d3; }
}
__global__ void fill_kernel(const void* __restrict__ ei,
                            int* __restrict__ cursor, int* __restrict__ csrsrc) {
    int e = blockIdx.x * blockDim.x + threadIdx.x;
    if (e >= N_EDGES) return;
    int s = load_idx(ei, e);
    int d = load_idx(ei, (long long)N_EDGES + e);
    csrsrc[atomicAdd(&cursor[d], 1)] = s;
}

// ===========================================================================
// fp32 -> fp16 mirror convert (one float4 -> two half2 per thread)
// ===========================================================================
__global__ void tohalf_kernel(const float* __restrict__ src, __half2* __restrict__ dst) {
    const int i = blockIdx.x * blockDim.x + threadIdx.x;   // float4 index
    if (i >= N_NODES * 32) return;
    float4 v = ((const float4*)src)[i];
    dst[2 * i + 0] = __floats2half2_rn(v.x, v.y);
    dst[2 * i + 1] = __floats2half2_rn(v.z, v.w);
}

// ===========================================================================
// GIN aggregation (gather): out[n] = self[n] (fp32) + sum_nbr h16[src] (fp16).
// One warp per node; lane owns 4 feature cols. Neighbor rows are 256B.
// ===========================================================================
__global__ void __launch_bounds__(256)
agg_kernel(const float* __restrict__ self, const __half2* __restrict__ nbr,
           float* __restrict__ out,
           const int* __restrict__ rowptr, const int* __restrict__ csrsrc) {
    const int n = blockIdx.x * 8 + (threadIdx.x >> 5);
    if (n >= N_NODES) return;
    const int lane = threadIdx.x & 31;
    const int beg = rowptr[n];
    const int end = rowptr[n + 1];
    float4 acc = ((const float4*)(self + (size_t)n * FEAT))[lane];
    for (int base = beg; base < end; base += 32) {
        const int cnt = min(32, end - base);
        int sid = (base + lane < end) ? csrsrc[base + lane] : 0;
#pragma unroll 4
        for (int j = 0; j < cnt; j++) {
            int s = __shfl_sync(0xffffffffu, sid, j);
            uint2 w = ((const uint2*)(nbr + (size_t)s * 64))[lane];
            __half2 p0 = *reinterpret_cast<__half2*>(&w.x);
            __half2 p1 = *reinterpret_cast<__half2*>(&w.y);
            float2 f0 = __half22float2(p0);
            float2 f1 = __half22float2(p1);
            acc.x += f0.x; acc.y += f0.y; acc.z += f1.x; acc.w += f1.y;
        }
    }
    ((float4*)(out + (size_t)n * FEAT))[lane] = acc;
}

// ===========================================================================
// Fused persistent MLP (two bf16-split HMMA GEMMs), R8 structure:
//   C = relu( relu(A@W1^T + b1) @ W2^T + b2 )
// cp.async fp32 stage -> split-convert; optional fp16 mirror of C (h16out).
// ===========================================================================
#define SAB 136
#define WTILE_B (128 * SAB * 2)
#define ATILE_B (64 * SAB * 2)
#define STG_F   132
#define SMF_B1   0
#define SMF_B2   512
#define SMF_W1H  1024
#define SMF_W1L  (SMF_W1H + WTILE_B)
#define SMF_W2H  (SMF_W1H + 2 * WTILE_B)
#define SMF_W2L  (SMF_W1H + 3 * WTILE_B)
#define SMF_AH   (SMF_W1H + 4 * WTILE_B)
#define SMF_AL   (SMF_AH + ATILE_B)
#define SMF_STG  (SMF_AL + ATILE_B)
#define SMF_TOTAL (SMF_STG + 64 * STG_F * 4)  // 208896
#define GEMM_GRID 148

__global__ void __launch_bounds__(256)
mlp_fused_kernel(const float* __restrict__ A,
                 const float* __restrict__ W1, const float* __restrict__ b1,
                 const float* __restrict__ W2, const float* __restrict__ b2,
                 float* __restrict__ C, __half2* __restrict__ h16out, int M) {
    extern __shared__ char smem[];
    const uint32_t sb = smem_u32(smem);
    const int tid = threadIdx.x;
    const int lane = tid & 31;
    const int wid = tid >> 5;
    const int numTiles = (M + 63) >> 6;

    float* stg = (float*)(smem + SMF_STG);

    int tile = blockIdx.x;
    if (tile < numTiles) {
        const int row0 = tile << 6;
#pragma unroll
        for (int j = 0; j < 8; j++) {
            const int i = tid + j * 256;
            const int r = i >> 5, c16 = i & 31;
            if (row0 + r < M)
                cp16(sb + SMF_STG + (uint32_t)(r * STG_F + c16 * 4) * 4,
                     A + (size_t)(row0 + r) * FEAT + c16 * 4);
        }
    }
    CP_COMMIT();

    if (tid < 128) ((float*)(smem + SMF_B1))[tid] = b1[tid];
    else           ((float*)(smem + SMF_B2))[tid - 128] = b2[tid - 128];
    {
        const int r = tid >> 1;
        const int half = tid & 1;
        const float4* w1row = (const float4*)(W1 + (size_t)r * FEAT);
        const float4* w2row = (const float4*)(W2 + (size_t)r * FEAT);
#pragma unroll
        for (int j = 0; j < 16; j++) {
            const int col = half * 64 + j * 4;
            const uint32_t off = (uint32_t)(r * SAB + col) * 2;
            float4 v1 = w1row[half * 16 + j];
            float a0 = __bfloat162float(__float2bfloat16_rn(v1.x));
            float a1 = __bfloat162float(__float2bfloat16_rn(v1.y));
            float a2 = __bfloat162float(__float2bfloat16_rn(v1.z));
            float a3 = __bfloat162float(__float2bfloat16_rn(v1.w));
            *(uint2*)(smem + SMF_W1H + off) = make_uint2(pack_bf16(a0, a1), pack_bf16(a2, a3));
            *(uint2*)(smem + SMF_W1L + off) =
                make_uint2(pack_bf16(v1.x - a0, v1.y - a1), pack_bf16(v1.z - a2, v1.w - a3));
            float4 v2 = w2row[half * 16 + j];
            float c0 = __bfloat162float(__float2bfloat16_rn(v2.x));
            float c1 = __bfloat162float(__float2bfloat16_rn(v2.y));
            float c2 = __bfloat162float(__float2bfloat16_rn(v2.z));
            float c3 = __bfloat162float(__float2bfloat16_rn(v2.w));
            *(uint2*)(smem + SMF_W2H + off) = make_uint2(pack_bf16(c0, c1), pack_bf16(c2, c3));
            *(uint2*)(smem + SMF_W2L + off) =
                make_uint2(pack_bf16(v2.x - c0, v2.y - c1), pack_bf16(v2.z - c2, v2.w - c3));
        }
    }

    const int m0 = (wid & 1) * 32;
    const int n0 = (wid >> 1) * 32;
    const int g = lane >> 3, rr = lane & 7;
    uint32_t aH0[2], aL0[2], b1H[2], b1L[2], b2H[2], b2L[2];
#pragma unroll
    for (int mb = 0; mb < 2; mb++) {
        const uint32_t o = (uint32_t)((m0 + mb * 16 + (g & 1) * 8 + rr) * SAB + (g >> 1) * 8) * 2;
        aH0[mb] = sb + SMF_AH + o;
        aL0[mb] = sb + SMF_AL + o;
    }
#pragma unroll
    for (int p = 0; p < 2; p++) {
        const uint32_t o = (uint32_t)((n0 + p * 16 + (g >> 1) * 8 + rr) * SAB + (g & 1) * 8) * 2;
        b1H[p] = sb + SMF_W1H + o;
        b1L[p] = sb + SMF_W1L + o;
        b2H[p] = sb + SMF_W2H + o;
        b2L[p] = sb + SMF_W2L + o;
    }
    const float* bs1 = (const float*)(smem + SMF_B1);
    const float* bs2 = (const float*)(smem + SMF_B2);

    for (; tile < numTiles; tile += GEMM_GRID) {
        const int row0 = tile << 6;

        CP_WAIT0();
        __syncthreads();

        {
            const int r = tid >> 2;
            const int q = tid & 3;
            const bool in = (row0 + r < M);
            const float* srow = stg + r * STG_F + q * 32;
#pragma unroll
            for (int j = 0; j < 8; j++) {
                const int col = q * 32 + j * 4;
                const uint32_t off = (uint32_t)(r * SAB + col) * 2;
                float4 va = in ? *(const float4*)(srow + j * 4) : make_float4(0.f, 0.f, 0.f, 0.f);
                float h0 = __bfloat162float(__float2bfloat16_rn(va.x));
                float h1 = __bfloat162float(__float2bfloat16_rn(va.y));
                float h2 = __bfloat162float(__float2bfloat16_rn(va.z));
                float h3 = __bfloat162float(__float2bfloat16_rn(va.w));
                *(uint2*)(smem + SMF_AH + off) = make_uint2(pack_bf16(h0, h1), pack_bf16(h2, h3));
                *(uint2*)(smem + SMF_AL + off) =
                    make_uint2(pack_bf16(va.x - h0, va.y - h1), pack_bf16(va.z - h2, va.w - h3));
            }
        }
        __syncthreads();

        const int nt = tile + GEMM_GRID;
        if (nt < numTiles) {
            const int nrow0 = nt << 6;
#pragma unroll
            for (int j = 0; j < 8; j++) {
                const int i = tid + j * 256;
                const int r = i >> 5, c16 = i & 31;
                if (nrow0 + r < M)
                    cp16(sb + SMF_STG + (uint32_t)(r * STG_F + c16 * 4) * 4,
                         A + (size_t)(nrow0 + r) * FEAT + c16 * 4);
            }
        }
        CP_COMMIT();

        float acc[2][4][4];
#pragma unroll
        for (int mb = 0; mb < 2; mb++)
#pragma unroll
            for (int o = 0; o < 4; o++)
#pragma unroll
                for (int q = 0; q < 4; q++) acc[mb][o][q] = 0.f;
        {
            uint32_t aH_[2] = {aH0[0], aH0[1]}, aL_[2] = {aL0[0], aL0[1]};
            uint32_t bH_[2] = {b1H[0], b1H[1]}, bL_[2] = {b1L[0], b1L[1]};
#pragma unroll
            for (int kk = 0; kk < 8; kk++) {
                uint32_t ah[2][4], al[2][4], bb[2][4];
                ldsm_x4(ah[0], aH_[0]); ldsm_x4(ah[1], aH_[1]);
                ldsm_x4(al[0], aL_[0]); ldsm_x4(al[1], aL_[1]);
                ldsm_x4(bb[0], bH_[0]); ldsm_x4(bb[1], bH_[1]);
#pragma unroll
                for (int mb = 0; mb < 2; mb++)
#pragma unroll
                    for (int o = 0; o < 4; o++) {
                        const uint32_t* b = &bb[o >> 1][(o & 1) * 2];
                        mma_bf16(acc[mb][o], ah[mb], b);
                        mma_bf16(acc[mb][o], al[mb], b);
                    }
                ldsm_x4(bb[0], bL_[0]); ldsm_x4(bb[1], bL_[1]);
#pragma unroll
                for (int mb = 0; mb < 2; mb++)
#pragma unroll
                    for (int o = 0; o < 4; o++)
                        mma_bf16(acc[mb][o], ah[mb], &bb[o >> 1][(o & 1) * 2]);
#pragma unroll
                for (int i = 0; i < 2; i++) { aH_[i] += 32; aL_[i] += 32; bH_[i] += 32; bL_[i] += 32; }
            }
        }
        __syncthreads();

#pragma unroll
        for (int mb = 0; mb < 2; mb++) {
            const int r0 = m0 + mb * 16 + (lane >> 2);
#pragma unroll
            for (int o = 0; o < 4; o++) {
                const int col = n0 + o * 8 + (lane & 3) * 2;
                const float c0 = bs1[col], c1 = bs1[col + 1];
                const uint32_t off0 = (uint32_t)(r0 * SAB + col) * 2;
                const uint32_t off8 = (uint32_t)((r0 + 8) * SAB + col) * 2;
                float v0 = fmaxf(acc[mb][o][0] + c0, 0.f);
                float v1 = fmaxf(acc[mb][o][1] + c1, 0.f);
                float h0 = __bfloat162float(__float2bfloat16_rn(v0));
                float h1 = __bfloat162float(__float2bfloat16_rn(v1));
                *(uint32_t*)(smem + SMF_AH + off0) = pack_bf16(h0, h1);
                *(uint32_t*)(smem + SMF_AL + off0) = pack_bf16(v0 - h0, v1 - h1);
                float v2 = fmaxf(acc[mb][o][2] + c0, 0.f);
                float v3 = fmaxf(acc[mb][o][3] + c1, 0.f);
                float h2 = __bfloat162float(__float2bfloat16_rn(v2));
                float h3 = __bfloat162float(__float2bfloat16_rn(v3));
                *(uint32_t*)(smem + SMF_AH + off8) = pack_bf16(h2, h3);
                *(uint32_t*)(smem + SMF_AL + off8) = pack_bf16(v2 - h2, v3 - h3);
            }
        }
        __syncthreads();

#pragma unroll
        for (int mb = 0; mb < 2; mb++)
#pragma unroll
            for (int o = 0; o < 4; o++)
#pragma unroll
                for (int q = 0; q < 4; q++) acc[mb][o][q] = 0.f;
        {
            uint32_t aH_[2] = {aH0[0], aH0[1]}, aL_[2] = {aL0[0], aL0[1]};
            uint32_t bH_[2] = {b2H[0], b2H[1]}, bL_[2] = {b2L[0], b2L[1]};
#pragma unroll
            for (int kk = 0; kk < 8; kk++) {
                uint32_t ah[2][4], al[2][4], bb[2][4];
                ldsm_x4(ah[0], aH_[0]); ldsm_x4(ah[1], aH_[1]);
                ldsm_x4(al[0], aL_[0]); ldsm_x4(al[1], aL_[1]);
                ldsm_x4(bb[0], bH_[0]); ldsm_x4(bb[1], bH_[1]);
#pragma unroll
                for (int mb = 0; mb < 2; mb++)
#pragma unroll
                    for (int o = 0; o < 4; o++) {
                        const uint32_t* b = &bb[o >> 1][(o & 1) * 2];
                        mma_bf16(acc[mb][o], ah[mb], b);
                        mma_bf16(acc[mb][o], al[mb], b);
                    }
                ldsm_x4(bb[0], bL_[0]); ldsm_x4(bb[1], bL_[1]);
#pragma unroll
                for (int mb = 0; mb < 2; mb++)
#pragma unroll
                    for (int o = 0; o < 4; o++)
                        mma_bf16(acc[mb][o], ah[mb], &bb[o >> 1][(o & 1) * 2]);
#pragma unroll
                for (int i = 0; i < 2; i++) { aH_[i] += 32; aL_[i] += 32; bH_[i] += 32; bL_[i] += 32; }
            }
        }
        __syncthreads();

#pragma unroll
        for (int mb = 0; mb < 2; mb++) {
            const int rbase = row0 + m0 + mb * 16 + (lane >> 2);
#pragma unroll
            for (int o = 0; o < 4; o++) {
                const int col = n0 + o * 8 + (lane & 3) * 2;
                const float c0 = bs2[col], c1 = bs2[col + 1];
                if (rbase < M) {
                    float v0 = fmaxf(acc[mb][o][0] + c0, 0.f);
                    float v1 = fmaxf(acc[mb][o][1] + c1, 0.f);
                    *(float2*)(C + (size_t)rbase * FEAT + col) = make_float2(v0, v1);
                    if (h16out)
                        h16out[(size_t)rbase * 64 + (col >> 1)] = __floats2half2_rn(v0, v1);
                }
                if (rbase + 8 < M) {
                    float v2 = fmaxf(acc[mb][o][2] + c0, 0.f);
                    float v3 = fmaxf(acc[mb][o][3] + c1, 0.f);
                    *(float2*)(C + (size_t)(rbase + 8) * FEAT + col) = make_float2(v2, v3);
                    if (h16out)
                        h16out[(size_t)(rbase + 8) * 64 + (col >> 1)] = __floats2half2_rn(v2, v3);
                }
            }
        }
    }
}

// ===========================================================================
// Global mean pool per graph (batch sorted -> binary search)
// ===========================================================================
__global__ void pool_kernel(const float* __restrict__ h, const void* __restrict__ batch,
                            float* __restrict__ out_pool) {
    const int g = blockIdx.x;
    const int c = threadIdx.x;
    const int is64 = g_idx64;
    const long long* b64 = (const long long*)batch;
    const int* b32 = (const int*)batch;

    int lo = 0, hi = N_NODES;
    while (lo < hi) {
        int mid = (lo + hi) >> 1;
        long long v = is64 ? b64[mid] : (long long)b32[mid];
        if (v < (long long)g) lo = mid + 1; else hi = mid;
    }
    const int start = lo;
    hi = N_NODES;
    while (lo < hi) {
        int mid = (lo + hi) >> 1;
        long long v = is64 ? b64[mid] : (long long)b32[mid];
        if (v < (long long)g + 1) lo = mid + 1; else hi = mid;
    }
    const int end = lo;

    float s = 0.f;
    for (int r = start; r < end; r++) s += h[(size_t)r * FEAT + c];
    out_pool[g * FEAT + c] = s / fmaxf((float)(end - start), 1.f);
}

// ===========================================================================
extern "C" void kernel_launch(void* const* d_in, const int* in_sizes, int n_in,
                              void* d_out, int out_size) {
    const float* x   = (const float*)d_in[0];
    const void*  ei  = d_in[1];
    const void*  bat = d_in[2];
    const float* W1 = (const float*)d_in[3];
    const float* b1 = (const float*)d_in[4];
    const float* W2 = (const float*)d_in[5];
    const float* b2 = (const float*)d_in[6];
    const float* W3 = (const float*)d_in[7];
    const float* b3 = (const float*)d_in[8];
    const float* W4 = (const float*)d_in[9];
    const float* b4 = (const float*)d_in[10];

    float* out      = (float*)d_out;
    float* out_pool = out;
    float* out_h    = out + N_GRAPHS * FEAT;

    float *bufA, *bufB;
    __half2* h16;
    int *deg, *rowptr, *cursor, *csrsrc, *blocksum, *blockoff;
    cudaGetSymbolAddress((void**)&bufA, g_bufA);
    cudaGetSymbolAddress((void**)&bufB, g_bufB);
    cudaGetSymbolAddress((void**)&h16, g_h16);
    cudaGetSymbolAddress((void**)&deg, g_deg);
    cudaGetSymbolAddress((void**)&rowptr, g_rowptr);
    cudaGetSymbolAddress((void**)&cursor, g_cursor);
    cudaGetSymbolAddress((void**)&csrsrc, g_csrsrc);
    cudaGetSymbolAddress((void**)&blocksum, g_blocksum);
    cudaGetSymbolAddress((void**)&blockoff, g_blockoff);

    cudaFuncSetAttribute(mlp_fused_kernel,
                         cudaFuncAttributeMaxDynamicSharedMemorySize, SMF_TOTAL);

    const int edge_blocks = (N_EDGES + 255) / 256;
    const int cvt_blocks = (N_NODES * 32 + 255) / 256;
    const int agg_blocks = (N_NODES + 7) / 8;

    // ---- CSR build ----
    detect_kernel<<<1, 32>>>((const int*)ei);
    cudaMemsetAsync(deg, 0, N_NODES * sizeof(int));
    hist_kernel<<<edge_blocks, 256>>>(ei, deg);
    scanA_kernel<<<SCAN_BLOCKS, 256>>>(deg, blocksum);
    scanB_kernel<<<1, 128>>>(blocksum, blockoff, rowptr);
    scanC_kernel<<<SCAN_BLOCKS, 256>>>(deg, blockoff, rowptr, cursor);
    fill_kernel<<<edge_blocks, 256>>>(ei, cursor, csrsrc);

    // ---- Layer 1: fp16 mirror of x, gather, fused MLP (emits fp16 mirror of h1) ----
    tohalf_kernel<<<cvt_blocks, 256>>>(x, h16);
    agg_kernel<<<agg_blocks, 256>>>(x, h16, bufA, rowptr, csrsrc);
    mlp_fused_kernel<<<GEMM_GRID, 256, SMF_TOTAL>>>(bufA, W1, b1, W2, b2,
                                                    bufB, h16, N_NODES);

    // ---- Layer 2: gather from h1's fp16 mirror, fused MLP -> out_h ----
    agg_kernel<<<agg_blocks, 256>>>(bufB, h16, bufA, rowptr, csrsrc);
    mlp_fused_kernel<<<GEMM_GRID, 256, SMF_TOTAL>>>(bufA, W3, b3, W4, b4,
                                                    out_h, (__half2*)nullptr, N_NODES);

    // ---- Global mean pool ----
    pool_kernel<<<N_GRAPHS, FEAT>>>(out_h, bat, out_pool);
}

// round 15
// speedup vs baseline: 2.1982x; 1.1956x over previous
#include <cuda_runtime.h>
#include <cuda_bf16.h>
#include <cstdint>

#define N_NODES 100000
#define N_EDGES 1600000
#define FEAT 128
#define N_GRAPHS 100
#define POOL_SEGS 8

#define SCAN_ITEMS 1024
#define SCAN_BLOCKS ((N_NODES + SCAN_ITEMS - 1) / SCAN_ITEMS)  // 98

// Scratch (allocation-free rule: __device__ globals)
__device__ float g_bufA[(size_t)N_NODES * FEAT];
__device__ float g_bufB[(size_t)N_NODES * FEAT];
__device__ float g_poolacc[N_GRAPHS * FEAT];
__device__ int   g_deg[N_NODES];
__device__ int   g_rowptr[N_NODES + 1];
__device__ int   g_cursor[N_NODES];
__device__ int   g_csrsrc[N_EDGES];
__device__ int   g_blocksum[SCAN_BLOCKS];
__device__ int   g_blockoff[SCAN_BLOCKS];
__device__ int   g_idx64;

// ===========================================================================
// Helpers
// ===========================================================================
__device__ __forceinline__ uint32_t smem_u32(const void* p) {
    uint32_t a;
    asm("{ .reg .u64 t; cvta.to.shared.u64 t, %1; cvt.u32.u64 %0, t; }" : "=r"(a) : "l"(p));
    return a;
}
__device__ __forceinline__ uint32_t pack_bf16(float a, float b) {  // {lo=a, hi=b}
    uint32_t r;
    asm("cvt.rn.bf16x2.f32 %0, %1, %2;" : "=r"(r) : "f"(b), "f"(a));
    return r;
}
__device__ __forceinline__ void ldsm_x4(uint32_t* r, uint32_t addr) {
    asm volatile("ldmatrix.sync.aligned.m8n8.x4.shared.b16 {%0,%1,%2,%3}, [%4];"
        : "=r"(r[0]), "=r"(r[1]), "=r"(r[2]), "=r"(r[3]) : "r"(addr));
}
__device__ __forceinline__ void mma_bf16(float* c, const uint32_t* a, const uint32_t* b) {
    asm volatile("mma.sync.aligned.m16n8k16.row.col.f32.bf16.bf16.f32 "
        "{%0,%1,%2,%3}, {%4,%5,%6,%7}, {%8,%9}, {%0,%1,%2,%3};"
        : "+f"(c[0]), "+f"(c[1]), "+f"(c[2]), "+f"(c[3])
        : "r"(a[0]), "r"(a[1]), "r"(a[2]), "r"(a[3]), "r"(b[0]), "r"(b[1]));
}
__device__ __forceinline__ void cp16(uint32_t saddr, const void* gptr) {
    asm volatile("cp.async.cg.shared.global [%0], [%1], 16;" :: "r"(saddr), "l"(gptr));
}
#define CP_COMMIT() asm volatile("cp.async.commit_group;" ::: "memory")
#define CP_WAIT0()  asm volatile("cp.async.wait_group 0;" ::: "memory")

// ===========================================================================
// Index dtype detector (int64 little-endian => odd words zero). 1 warp.
// ===========================================================================
__global__ void detect_kernel(const int* __restrict__ ei_words) {
    const int lane = threadIdx.x;
    int ok = 1;
#pragma unroll
    for (int j = 0; j < 16; j++) {
        int i = j * 32 + lane;
        int lo = ei_words[2 * i];
        int hi = ei_words[2 * i + 1];
        if (hi != 0 || lo < 0 || lo >= N_NODES) ok = 0;
    }
    int all = __all_sync(0xffffffffu, ok);
    if (lane == 0) g_idx64 = all;
}
__device__ __forceinline__ int load_idx(const void* p, long long i) {
    return g_idx64 ? (int)((const long long*)p)[i] : ((const int*)p)[i];
}

// ===========================================================================
// CSR build
// ===========================================================================
__global__ void hist_kernel(const void* __restrict__ ei, int* __restrict__ deg) {
    int e = blockIdx.x * blockDim.x + threadIdx.x;
    if (e >= N_EDGES) return;
    atomicAdd(&deg[load_idx(ei, (long long)N_EDGES + e)], 1);
}
__global__ void scanA_kernel(const int* __restrict__ deg, int* __restrict__ blocksum) {
    __shared__ int red[256];
    const int t = threadIdx.x;
    const int base = blockIdx.x * SCAN_ITEMS;
    int s = 0;
#pragma unroll
    for (int j = 0; j < 4; j++) {
        int i = base + t + j * 256;
        if (i < N_NODES) s += deg[i];
    }
    red[t] = s;
    __syncthreads();
    for (int off = 128; off > 0; off >>= 1) {
        if (t < off) red[t] += red[t + off];
        __syncthreads();
    }
    if (t == 0) blocksum[blockIdx.x] = red[0];
}
__global__ void scanB_kernel(const int* __restrict__ blocksum,
                             int* __restrict__ blockoff, int* __restrict__ rowptr) {
    __shared__ int v[128];
    const int t = threadIdx.x;
    v[t] = (t < SCAN_BLOCKS) ? blocksum[t] : 0;
    __syncthreads();
    int mine = v[t];
    for (int off = 1; off < 128; off <<= 1) {
        int tmp = (t >= off) ? v[t - off] : 0;
        __syncthreads();
        v[t] += tmp;
        __syncthreads();
    }
    if (t < SCAN_BLOCKS) blockoff[t] = v[t] - mine;
    if (t == 127) rowptr[N_NODES] = v[127];
}
__global__ void scanC_kernel(const int* __restrict__ deg, const int* __restrict__ blockoff,
                             int* __restrict__ rowptr, int* __restrict__ cursor) {
    __shared__ int ts[256];
    const int t = threadIdx.x;
    const int base = blockIdx.x * SCAN_ITEMS + t * 4;
    int d0 = 0, d1 = 0, d2 = 0, d3 = 0;
    if (base + 0 < N_NODES) d0 = deg[base + 0];
    if (base + 1 < N_NODES) d1 = deg[base + 1];
    if (base + 2 < N_NODES) d2 = deg[base + 2];
    if (base + 3 < N_NODES) d3 = deg[base + 3];
    int tot = d0 + d1 + d2 + d3;
    ts[t] = tot;
    __syncthreads();
    for (int off = 1; off < 256; off <<= 1) {
        int tmp = (t >= off) ? ts[t - off] : 0;
        __syncthreads();
        ts[t] += tmp;
        __syncthreads();
    }
    int run = blockoff[blockIdx.x] + ts[t] - tot;
    if (base + 0 < N_NODES) { rowptr[base + 0] = run; cursor[base + 0] = run; run += d0; }
    if (base + 1 < N_NODES) { rowptr[base + 1] = run; cursor[base + 1] = run; run += d1; }
    if (base + 2 < N_NODES) { rowptr[base + 2] = run; cursor[base + 2] = run; run += d2; }
    if (base + 3 < N_NODES) { rowptr[base + 3] = run; cursor[base + 3] = run; run += d3; }
}
__global__ void fill_kernel(const void* __restrict__ ei,
                            int* __restrict__ cursor, int* __restrict__ csrsrc) {
    int e = blockIdx.x * blockDim.x + threadIdx.x;
    if (e >= N_EDGES) return;
    int s = load_idx(ei, e);
    int d = load_idx(ei, (long long)N_EDGES + e);
    csrsrc[atomicAdd(&cursor[d], 1)] = s;
}

// ===========================================================================
// GIN aggregation (gather): out[n] = x[n] + sum_{e in CSR[n]} x[src[e]].
// One warp per node; lane owns a float4. csrsrc chunk loads software-pipelined.
// ===========================================================================
__global__ void __launch_bounds__(256)
agg_kernel(const float* __restrict__ x, float* __restrict__ out,
           const int* __restrict__ rowptr, const int* __restrict__ csrsrc) {
    const int n = blockIdx.x * 8 + (threadIdx.x >> 5);
    if (n >= N_NODES) return;
    const int lane = threadIdx.x & 31;
    const int beg = rowptr[n];
    const int end = rowptr[n + 1];
    float4 acc = ((const float4*)(x + (size_t)n * FEAT))[lane];

    int base = beg;
    int sid = (base + lane < end) ? csrsrc[base + lane] : 0;  // prefetched chunk
    while (base < end) {
        const int cnt = min(32, end - base);
        const int nb = base + 32;
        int sid_next = (nb + lane < end) ? csrsrc[nb + lane] : 0;  // prefetch next
#pragma unroll 4
        for (int j = 0; j < cnt; j++) {
            int s = __shfl_sync(0xffffffffu, sid, j);
            float4 v = ((const float4*)(x + (size_t)s * FEAT))[lane];
            acc.x += v.x; acc.y += v.y; acc.z += v.z; acc.w += v.w;
        }
        sid = sid_next;
        base = nb;
    }
    ((float4*)(out + (size_t)n * FEAT))[lane] = acc;
}

// ===========================================================================
// Fused persistent MLP (two bf16-split HMMA GEMMs) — exact R8 structure:
//   C = relu( relu(A@W1^T + b1) @ W2^T + b2 )
// ===========================================================================
#define SAB 136
#define WTILE_B (128 * SAB * 2)
#define ATILE_B (64 * SAB * 2)
#define STG_F   132
#define SMF_B1   0
#define SMF_B2   512
#define SMF_W1H  1024
#define SMF_W1L  (SMF_W1H + WTILE_B)
#define SMF_W2H  (SMF_W1H + 2 * WTILE_B)
#define SMF_W2L  (SMF_W1H + 3 * WTILE_B)
#define SMF_AH   (SMF_W1H + 4 * WTILE_B)
#define SMF_AL   (SMF_AH + ATILE_B)
#define SMF_STG  (SMF_AL + ATILE_B)
#define SMF_TOTAL (SMF_STG + 64 * STG_F * 4)  // 208896
#define GEMM_GRID 148

__global__ void __launch_bounds__(256)
mlp_fused_kernel(const float* __restrict__ A,
                 const float* __restrict__ W1, const float* __restrict__ b1,
                 const float* __restrict__ W2, const float* __restrict__ b2,
                 float* __restrict__ C, int M) {
    extern __shared__ char smem[];
    const uint32_t sb = smem_u32(smem);
    const int tid = threadIdx.x;
    const int lane = tid & 31;
    const int wid = tid >> 5;
    const int numTiles = (M + 63) >> 6;

    float* stg = (float*)(smem + SMF_STG);

    int tile = blockIdx.x;
    if (tile < numTiles) {
        const int row0 = tile << 6;
#pragma unroll
        for (int j = 0; j < 8; j++) {
            const int i = tid + j * 256;
            const int r = i >> 5, c16 = i & 31;
            if (row0 + r < M)
                cp16(sb + SMF_STG + (uint32_t)(r * STG_F + c16 * 4) * 4,
                     A + (size_t)(row0 + r) * FEAT + c16 * 4);
        }
    }
    CP_COMMIT();

    if (tid < 128) ((float*)(smem + SMF_B1))[tid] = b1[tid];
    else           ((float*)(smem + SMF_B2))[tid - 128] = b2[tid - 128];
    {
        const int r = tid >> 1;
        const int half = tid & 1;
        const float4* w1row = (const float4*)(W1 + (size_t)r * FEAT);
        const float4* w2row = (const float4*)(W2 + (size_t)r * FEAT);
#pragma unroll
        for (int j = 0; j < 16; j++) {
            const int col = half * 64 + j * 4;
            const uint32_t off = (uint32_t)(r * SAB + col) * 2;
            float4 v1 = w1row[half * 16 + j];
            float a0 = __bfloat162float(__float2bfloat16_rn(v1.x));
            float a1 = __bfloat162float(__float2bfloat16_rn(v1.y));
            float a2 = __bfloat162float(__float2bfloat16_rn(v1.z));
            float a3 = __bfloat162float(__float2bfloat16_rn(v1.w));
            *(uint2*)(smem + SMF_W1H + off) = make_uint2(pack_bf16(a0, a1), pack_bf16(a2, a3));
            *(uint2*)(smem + SMF_W1L + off) =
                make_uint2(pack_bf16(v1.x - a0, v1.y - a1), pack_bf16(v1.z - a2, v1.w - a3));
            float4 v2 = w2row[half * 16 + j];
            float c0 = __bfloat162float(__float2bfloat16_rn(v2.x));
            float c1 = __bfloat162float(__float2bfloat16_rn(v2.y));
            float c2 = __bfloat162float(__float2bfloat16_rn(v2.z));
            float c3 = __bfloat162float(__float2bfloat16_rn(v2.w));
            *(uint2*)(smem + SMF_W2H + off) = make_uint2(pack_bf16(c0, c1), pack_bf16(c2, c3));
            *(uint2*)(smem + SMF_W2L + off) =
                make_uint2(pack_bf16(v2.x - c0, v2.y - c1), pack_bf16(v2.z - c2, v2.w - c3));
        }
    }

    const int m0 = (wid & 1) * 32;
    const int n0 = (wid >> 1) * 32;
    const int g = lane >> 3, rr = lane & 7;
    uint32_t aH0[2], aL0[2], b1H[2], b1L[2], b2H[2], b2L[2];
#pragma unroll
    for (int mb = 0; mb < 2; mb++) {
        const uint32_t o = (uint32_t)((m0 + mb * 16 + (g & 1) * 8 + rr) * SAB + (g >> 1) * 8) * 2;
        aH0[mb] = sb + SMF_AH + o;
        aL0[mb] = sb + SMF_AL + o;
    }
#pragma unroll
    for (int p = 0; p < 2; p++) {
        const uint32_t o = (uint32_t)((n0 + p * 16 + (g >> 1) * 8 + rr) * SAB + (g & 1) * 8) * 2;
        b1H[p] = sb + SMF_W1H + o;
        b1L[p] = sb + SMF_W1L + o;
        b2H[p] = sb + SMF_W2H + o;
        b2L[p] = sb + SMF_W2L + o;
    }
    const float* bs1 = (const float*)(smem + SMF_B1);
    const float* bs2 = (const float*)(smem + SMF_B2);

    for (; tile < numTiles; tile += GEMM_GRID) {
        const int row0 = tile << 6;

        CP_WAIT0();
        __syncthreads();

        {
            const int r = tid >> 2;
            const int q = tid & 3;
            const bool in = (row0 + r < M);
            const float* srow = stg + r * STG_F + q * 32;
#pragma unroll
            for (int j = 0; j < 8; j++) {
                const int col = q * 32 + j * 4;
                const uint32_t off = (uint32_t)(r * SAB + col) * 2;
                float4 va = in ? *(const float4*)(srow + j * 4) : make_float4(0.f, 0.f, 0.f, 0.f);
                float h0 = __bfloat162float(__float2bfloat16_rn(va.x));
                float h1 = __bfloat162float(__float2bfloat16_rn(va.y));
                float h2 = __bfloat162float(__float2bfloat16_rn(va.z));
                float h3 = __bfloat162float(__float2bfloat16_rn(va.w));
                *(uint2*)(smem + SMF_AH + off) = make_uint2(pack_bf16(h0, h1), pack_bf16(h2, h3));
                *(uint2*)(smem + SMF_AL + off) =
                    make_uint2(pack_bf16(va.x - h0, va.y - h1), pack_bf16(va.z - h2, va.w - h3));
            }
        }
        __syncthreads();

        const int nt = tile + GEMM_GRID;
        if (nt < numTiles) {
            const int nrow0 = nt << 6;
#pragma unroll
            for (int j = 0; j < 8; j++) {
                const int i = tid + j * 256;
                const int r = i >> 5, c16 = i & 31;
                if (nrow0 + r < M)
                    cp16(sb + SMF_STG + (uint32_t)(r * STG_F + c16 * 4) * 4,
                         A + (size_t)(nrow0 + r) * FEAT + c16 * 4);
            }
        }
        CP_COMMIT();

        // ================= GEMM1 =================
        float acc[2][4][4];
#pragma unroll
        for (int mb = 0; mb < 2; mb++)
#pragma unroll
            for (int o = 0; o < 4; o++)
#pragma unroll
                for (int q = 0; q < 4; q++) acc[mb][o][q] = 0.f;
        {
            uint32_t aH_[2] = {aH0[0], aH0[1]}, aL_[2] = {aL0[0], aL0[1]};
            uint32_t bH_[2] = {b1H[0], b1H[1]}, bL_[2] = {b1L[0], b1L[1]};
#pragma unroll
            for (int kk = 0; kk < 8; kk++) {
                uint32_t ah[2][4], al[2][4], bb[2][4];
                ldsm_x4(ah[0], aH_[0]); ldsm_x4(ah[1], aH_[1]);
                ldsm_x4(al[0], aL_[0]); ldsm_x4(al[1], aL_[1]);
                ldsm_x4(bb[0], bH_[0]); ldsm_x4(bb[1], bH_[1]);
#pragma unroll
                for (int mb = 0; mb < 2; mb++)
#pragma unroll
                    for (int o = 0; o < 4; o++) {
                        const uint32_t* b = &bb[o >> 1][(o & 1) * 2];
                        mma_bf16(acc[mb][o], ah[mb], b);
                        mma_bf16(acc[mb][o], al[mb], b);
                    }
                ldsm_x4(bb[0], bL_[0]); ldsm_x4(bb[1], bL_[1]);
#pragma unroll
                for (int mb = 0; mb < 2; mb++)
#pragma unroll
                    for (int o = 0; o < 4; o++)
                        mma_bf16(acc[mb][o], ah[mb], &bb[o >> 1][(o & 1) * 2]);
#pragma unroll
                for (int i = 0; i < 2; i++) { aH_[i] += 32; aL_[i] += 32; bH_[i] += 32; bL_[i] += 32; }
            }
        }
        __syncthreads();

        // ---- h1 = relu(acc + b1) split-packed into A buffers ----
#pragma unroll
        for (int mb = 0; mb < 2; mb++) {
            const int r0 = m0 + mb * 16 + (lane >> 2);
#pragma unroll
            for (int o = 0; o < 4; o++) {
                const int col = n0 + o * 8 + (lane & 3) * 2;
                const float c0 = bs1[col], c1 = bs1[col + 1];
                const uint32_t off0 = (uint32_t)(r0 * SAB + col) * 2;
                const uint32_t off8 = (uint32_t)((r0 + 8) * SAB + col) * 2;
                float v0 = fmaxf(acc[mb][o][0] + c0, 0.f);
                float v1 = fmaxf(acc[mb][o][1] + c1, 0.f);
                float h0 = __bfloat162float(__float2bfloat16_rn(v0));
                float h1 = __bfloat162float(__float2bfloat16_rn(v1));
                *(uint32_t*)(smem + SMF_AH + off0) = pack_bf16(h0, h1);
                *(uint32_t*)(smem + SMF_AL + off0) = pack_bf16(v0 - h0, v1 - h1);
                float v2 = fmaxf(acc[mb][o][2] + c0, 0.f);
                float v3 = fmaxf(acc[mb][o][3] + c1, 0.f);
                float h2 = __bfloat162float(__float2bfloat16_rn(v2));
                float h3 = __bfloat162float(__float2bfloat16_rn(v3));
                *(uint32_t*)(smem + SMF_AH + off8) = pack_bf16(h2, h3);
                *(uint32_t*)(smem + SMF_AL + off8) = pack_bf16(v2 - h2, v3 - h3);
            }
        }
        __syncthreads();

        // ================= GEMM2 =================
#pragma unroll
        for (int mb = 0; mb < 2; mb++)
#pragma unroll
            for (int o = 0; o < 4; o++)
#pragma unroll
                for (int q = 0; q < 4; q++) acc[mb][o][q] = 0.f;
        {
            uint32_t aH_[2] = {aH0[0], aH0[1]}, aL_[2] = {aL0[0], aL0[1]};
            uint32_t bH_[2] = {b2H[0], b2H[1]}, bL_[2] = {b2L[0], b2L[1]};
#pragma unroll
            for (int kk = 0; kk < 8; kk++) {
                uint32_t ah[2][4], al[2][4], bb[2][4];
                ldsm_x4(ah[0], aH_[0]); ldsm_x4(ah[1], aH_[1]);
                ldsm_x4(al[0], aL_[0]); ldsm_x4(al[1], aL_[1]);
                ldsm_x4(bb[0], bH_[0]); ldsm_x4(bb[1], bH_[1]);
#pragma unroll
                for (int mb = 0; mb < 2; mb++)
#pragma unroll
                    for (int o = 0; o < 4; o++) {
                        const uint32_t* b = &bb[o >> 1][(o & 1) * 2];
                        mma_bf16(acc[mb][o], ah[mb], b);
                        mma_bf16(acc[mb][o], al[mb], b);
                    }
                ldsm_x4(bb[0], bL_[0]); ldsm_x4(bb[1], bL_[1]);
#pragma unroll
                for (int mb = 0; mb < 2; mb++)
#pragma unroll
                    for (int o = 0; o < 4; o++)
                        mma_bf16(acc[mb][o], ah[mb], &bb[o >> 1][(o & 1) * 2]);
#pragma unroll
                for (int i = 0; i < 2; i++) { aH_[i] += 32; aL_[i] += 32; bH_[i] += 32; bL_[i] += 32; }
            }
        }
        __syncthreads();

        // ---- epilogue: relu(acc + b2) -> C ----
#pragma unroll
        for (int mb = 0; mb < 2; mb++) {
            const int rbase = row0 + m0 + mb * 16 + (lane >> 2);
#pragma unroll
            for (int o = 0; o < 4; o++) {
                const int col = n0 + o * 8 + (lane & 3) * 2;
                const float c0 = bs2[col], c1 = bs2[col + 1];
                if (rbase < M) {
                    float2 v = make_float2(fmaxf(acc[mb][o][0] + c0, 0.f),
                                           fmaxf(acc[mb][o][1] + c1, 0.f));
                    *(float2*)(C + (size_t)rbase * FEAT + col) = v;
                }
                if (rbase + 8 < M) {
                    float2 v = make_float2(fmaxf(acc[mb][o][2] + c0, 0.f),
                                           fmaxf(acc[mb][o][3] + c1, 0.f));
                    *(float2*)(C + (size_t)(rbase + 8) * FEAT + col) = v;
                }
            }
        }
    }
}

// ===========================================================================
// Two-phase global mean pool: 800 partial-sum blocks + finalize divide.
// ===========================================================================
__device__ __forceinline__ void graph_range(const void* batch, int is64, int gph,
                                            int& start, int& end) {
    const long long* b64 = (const long long*)batch;
    const int* b32 = (const int*)batch;
    int lo = 0, hi = N_NODES;
    while (lo < hi) {
        int mid = (lo + hi) >> 1;
        long long v = is64 ? b64[mid] : (long long)b32[mid];
        if (v < (long long)gph) lo = mid + 1; else hi = mid;
    }
    start = lo;
    hi = N_NODES;
    while (lo < hi) {
        int mid = (lo + hi) >> 1;
        long long v = is64 ? b64[mid] : (long long)b32[mid];
        if (v < (long long)gph + 1) lo = mid + 1; else hi = mid;
    }
    end = lo;
}

__global__ void pool_partial_kernel(const float* __restrict__ h,
                                    const void* __restrict__ batch,
                                    float* __restrict__ poolacc) {
    const int gph = blockIdx.x;       // graph id
    const int seg = blockIdx.y;       // segment 0..POOL_SEGS-1
    const int c = threadIdx.x;        // feature 0..127
    int start, end;
    graph_range(batch, g_idx64, gph, start, end);
    const int len = end - start;
    const int s0 = start + (int)(((long long)len * seg) / POOL_SEGS);
    const int s1 = start + (int)(((long long)len * (seg + 1)) / POOL_SEGS);
    float s = 0.f;
    for (int r = s0; r < s1; r++) s += h[(size_t)r * FEAT + c];
    if (s1 > s0) atomicAdd(&poolacc[gph * FEAT + c], s);
}

__global__ void pool_final_kernel(const float* __restrict__ poolacc,
                                  const void* __restrict__ batch,
                                  float* __restrict__ out_pool) {
    const int gph = blockIdx.x;
    const int c = threadIdx.x;
    int start, end;
    graph_range(batch, g_idx64, gph, start, end);
    out_pool[gph * FEAT + c] = poolacc[gph * FEAT + c] / fmaxf((float)(end - start), 1.f);
}

// ===========================================================================
extern "C" void kernel_launch(void* const* d_in, const int* in_sizes, int n_in,
                              void* d_out, int out_size) {
    const float* x   = (const float*)d_in[0];
    const void*  ei  = d_in[1];
    const void*  bat = d_in[2];
    const float* W1 = (const float*)d_in[3];
    const float* b1 = (const float*)d_in[4];
    const float* W2 = (const float*)d_in[5];
    const float* b2 = (const float*)d_in[6];
    const float* W3 = (const float*)d_in[7];
    const float* b3 = (const float*)d_in[8];
    const float* W4 = (const float*)d_in[9];
    const float* b4 = (const float*)d_in[10];

    float* out      = (float*)d_out;
    float* out_pool = out;
    float* out_h    = out + N_GRAPHS * FEAT;

    float *bufA, *bufB, *poolacc;
    int *deg, *rowptr, *cursor, *csrsrc, *blocksum, *blockoff;
    cudaGetSymbolAddress((void**)&bufA, g_bufA);
    cudaGetSymbolAddress((void**)&bufB, g_bufB);
    cudaGetSymbolAddress((void**)&poolacc, g_poolacc);
    cudaGetSymbolAddress((void**)&deg, g_deg);
    cudaGetSymbolAddress((void**)&rowptr, g_rowptr);
    cudaGetSymbolAddress((void**)&cursor, g_cursor);
    cudaGetSymbolAddress((void**)&csrsrc, g_csrsrc);
    cudaGetSymbolAddress((void**)&blocksum, g_blocksum);
    cudaGetSymbolAddress((void**)&blockoff, g_blockoff);

    cudaFuncSetAttribute(mlp_fused_kernel,
                         cudaFuncAttributeMaxDynamicSharedMemorySize, SMF_TOTAL);

    const int edge_blocks = (N_EDGES + 255) / 256;
    const int agg_blocks = (N_NODES + 7) / 8;

    // ---- CSR build ----
    detect_kernel<<<1, 32>>>((const int*)ei);
    cudaMemsetAsync(deg, 0, N_NODES * sizeof(int));
    cudaMemsetAsync(poolacc, 0, N_GRAPHS * FEAT * sizeof(float));
    hist_kernel<<<edge_blocks, 256>>>(ei, deg);
    scanA_kernel<<<SCAN_BLOCKS, 256>>>(deg, blocksum);
    scanB_kernel<<<1, 128>>>(blocksum, blockoff, rowptr);
    scanC_kernel<<<SCAN_BLOCKS, 256>>>(deg, blockoff, rowptr, cursor);
    fill_kernel<<<edge_blocks, 256>>>(ei, cursor, csrsrc);

    // ---- Layer 1 ----
    agg_kernel<<<agg_blocks, 256>>>(x, bufA, rowptr, csrsrc);
    mlp_fused_kernel<<<GEMM_GRID, 256, SMF_TOTAL>>>(bufA, W1, b1, W2, b2, bufB, N_NODES);

    // ---- Layer 2 ----
    agg_kernel<<<agg_blocks, 256>>>(bufB, bufA, rowptr, csrsrc);
    mlp_fused_kernel<<<GEMM_GRID, 256, SMF_TOTAL>>>(bufA, W3, b3, W4, b4, out_h, N_NODES);

    // ---- Two-phase global mean pool ----
    dim3 pgrid(N_GRAPHS, POOL_SEGS);
    pool_partial_kernel<<<pgrid, FEAT>>>(out_h, bat, poolacc);
    pool_final_kernel<<<N_GRAPHS, FEAT>>>(poolacc, bat, out_pool);
}